// round 2
// baseline (speedup 1.0000x reference)
#include <cuda_runtime.h>
#include <math.h>

// ---------------- problem constants ----------------
#define NNODES   10000
#define F_IN     384
#define HID      256
#define OUT_D    128
#define ATT_H    64

// ---------------- scratch (device globals; no allocation allowed) ----------------
__device__ float g_h[NNODES * HID];
__device__ float g_agg[NNODES * HID];
__device__ float g_deg[NNODES];
__device__ float g_inv[NNODES];
__device__ float g_WaT[OUT_D * ATT_H];   // Wa1 transposed: [k][j] = Wa1[j][k]

// ---------------- utility: zero ----------------
__global__ void zero_kernel(float* __restrict__ p, int n) {
    int i = blockIdx.x * blockDim.x + threadIdx.x;
    if (i < n) p[i] = 0.0f;
}

// ---------------- fp32 GEMM: C[M,N] = relu(A[M,K] @ B[N,K]^T + bias[N]) ----------------
// A row-major MxK, B row-major NxK (weights as (out,in)), both K-contiguous.
#define BM 128
#define BN 64
#define BKK 16
#define TM 8
#define TN 4

__global__ __launch_bounds__(256) void gemm_relu_kernel(
    const float* __restrict__ A, const float* __restrict__ B,
    const float* __restrict__ bias, float* __restrict__ C,
    int M, int N, int K)
{
    __shared__ float As[BKK][BM + 4];
    __shared__ float Bs[BKK][BN + 4];

    const int n0 = blockIdx.x * BN;
    const int m0 = blockIdx.y * BM;
    const int tid = threadIdx.x;
    const int tx = tid & 15;    // n-dir, TN=4 -> 64
    const int ty = tid >> 4;    // m-dir, TM=8 -> 128

    float acc[TM][TN];
#pragma unroll
    for (int i = 0; i < TM; i++)
#pragma unroll
        for (int j = 0; j < TN; j++) acc[i][j] = 0.0f;

    for (int k0 = 0; k0 < K; k0 += BKK) {
        // load A tile: BM*BKK = 2048 elements, 8 per thread
#pragma unroll
        for (int it = 0; it < (BM * BKK) / 256; it++) {
            int t = tid + it * 256;
            int m = t / BKK, k = t % BKK;
            int gm = m0 + m;
            As[k][m] = (gm < M) ? A[(size_t)gm * K + k0 + k] : 0.0f;
        }
        // load B tile: BN*BKK = 1024 elements, 4 per thread (N is exact multiple of BN)
#pragma unroll
        for (int it = 0; it < (BN * BKK) / 256; it++) {
            int t = tid + it * 256;
            int n = t / BKK, k = t % BKK;
            Bs[k][n] = B[(size_t)(n0 + n) * K + k0 + k];
        }
        __syncthreads();

#pragma unroll
        for (int k = 0; k < BKK; k++) {
            float a[TM], b[TN];
#pragma unroll
            for (int i = 0; i < TM; i++) a[i] = As[k][ty * TM + i];
#pragma unroll
            for (int j = 0; j < TN; j++) b[j] = Bs[k][tx * TN + j];
#pragma unroll
            for (int i = 0; i < TM; i++)
#pragma unroll
                for (int j = 0; j < TN; j++) acc[i][j] = fmaf(a[i], b[j], acc[i][j]);
        }
        __syncthreads();
    }

#pragma unroll
    for (int i = 0; i < TM; i++) {
        int m = m0 + ty * TM + i;
        if (m >= M) continue;
#pragma unroll
        for (int j = 0; j < TN; j++) {
            int n = n0 + tx * TN + j;
            float v = acc[i][j] + bias[n];
            C[(size_t)m * N + n] = v > 0.0f ? v : 0.0f;
        }
    }
}

// ---------------- degree + inverse ----------------
__global__ void deg_kernel(const int* __restrict__ tgt, float* __restrict__ deg, int E) {
    int e = blockIdx.x * blockDim.x + threadIdx.x;
    if (e < E) atomicAdd(&deg[tgt[e]], 1.0f);
}

__global__ void inv_kernel(const float* __restrict__ deg, float* __restrict__ inv, int n) {
    int i = blockIdx.x * blockDim.x + threadIdx.x;
    if (i < n) inv[i] = 1.0f / (deg[i] + 1.0f);
}

// ---------------- scatter-add: agg[tgt] += h[src], 64 threads per edge (4 floats each) ----------------
__global__ __launch_bounds__(256) void scatter_kernel(
    const float* __restrict__ h, const int* __restrict__ src,
    const int* __restrict__ tgt, float* __restrict__ agg, int E)
{
    int idx = blockIdx.x * blockDim.x + threadIdx.x;
    int e = idx >> 6;
    if (e >= E) return;
    int c = (idx & 63) << 2;
    int s = src[e];
    int t = tgt[e];
    const float4 v = *reinterpret_cast<const float4*>(h + (size_t)s * HID + c);
    float* dst = agg + (size_t)t * HID + c;
    asm volatile("red.global.add.v4.f32 [%0], {%1,%2,%3,%4};"
                 :: "l"(dst), "f"(v.x), "f"(v.y), "f"(v.z), "f"(v.w)
                 : "memory");
}

// ---------------- combine: h = 0.7h + 0.3*agg*inv[row]; agg := 0 ----------------
__global__ void combine_kernel(float* __restrict__ h, float* __restrict__ agg,
                               const float* __restrict__ inv, int n4) {
    int i = blockIdx.x * blockDim.x + threadIdx.x;
    if (i >= n4) return;
    float s = 0.3f * inv[i >> 6];   // 64 float4 per 256-wide row
    float4 hv = reinterpret_cast<float4*>(h)[i];
    float4 av = reinterpret_cast<float4*>(agg)[i];
    hv.x = 0.7f * hv.x + s * av.x;
    hv.y = 0.7f * hv.y + s * av.y;
    hv.z = 0.7f * hv.z + s * av.z;
    hv.w = 0.7f * hv.w + s * av.w;
    reinterpret_cast<float4*>(h)[i] = hv;
    reinterpret_cast<float4*>(agg)[i] = make_float4(0.f, 0.f, 0.f, 0.f);
}

// ---------------- transpose Wa1 (64x128) -> WaT (128x64) ----------------
__global__ void transpose_wa1_kernel(const float* __restrict__ Wa1, float* __restrict__ WaT) {
    int idx = blockIdx.x * blockDim.x + threadIdx.x;
    if (idx >= OUT_D * ATT_H) return;
    int k = idx / ATT_H;   // 0..127
    int j = idx % ATT_H;   // 0..63
    WaT[idx] = Wa1[j * OUT_D + k];
}

// ---------------- attention: warp per node ----------------
__global__ __launch_bounds__(256) void attention_kernel(
    const float* __restrict__ out, const float* __restrict__ WaT,
    const float* __restrict__ ba1, const float* __restrict__ Wa2,
    const float* __restrict__ ba2, float* __restrict__ att, int N)
{
    int warp = (blockIdx.x * blockDim.x + threadIdx.x) >> 5;
    int lane = threadIdx.x & 31;
    if (warp >= N) return;
    const float* o = out + (size_t)warp * OUT_D;
    float acc0 = ba1[lane];
    float acc1 = ba1[lane + 32];
#pragma unroll 4
    for (int k = 0; k < OUT_D; k++) {
        float ov = __ldg(o + k);                     // broadcast within warp
        acc0 = fmaf(WaT[k * ATT_H + lane],      ov, acc0);
        acc1 = fmaf(WaT[k * ATT_H + lane + 32], ov, acc1);
    }
    acc0 = fmaxf(acc0, 0.0f) * Wa2[lane];
    acc1 = fmaxf(acc1, 0.0f) * Wa2[lane + 32];
    float s = acc0 + acc1;
#pragma unroll
    for (int off = 16; off; off >>= 1) s += __shfl_xor_sync(0xffffffffu, s, off);
    if (lane == 0) att[warp] = 1.0f / (1.0f + expf(-(s + ba2[0])));
}

// ---------------- launch ----------------
extern "C" void kernel_launch(void* const* d_in, const int* in_sizes, int n_in,
                              void* d_out, int out_size)
{
    const float* x    = (const float*)d_in[0];
    const int*   ei   = (const int*)d_in[1];     // (2, E) int32: [src | tgt]
    const float* W1   = (const float*)d_in[2];
    const float* b1   = (const float*)d_in[3];
    const float* W2   = (const float*)d_in[4];
    const float* b2   = (const float*)d_in[5];
    const float* Wa1  = (const float*)d_in[6];
    const float* ba1  = (const float*)d_in[7];
    const float* Wa2  = (const float*)d_in[8];
    const float* ba2  = (const float*)d_in[9];

    const int E = in_sizes[1] / 2;
    const int* src = ei;
    const int* tgt = ei + E;

    float* out_ptr = (float*)d_out;                        // (N, 128)
    float* att_ptr = out_ptr + (size_t)NNODES * OUT_D;     // (N, 1)

    float* h_p;   cudaGetSymbolAddress((void**)&h_p,   g_h);
    float* agg_p; cudaGetSymbolAddress((void**)&agg_p, g_agg);
    float* deg_p; cudaGetSymbolAddress((void**)&deg_p, g_deg);
    float* inv_p; cudaGetSymbolAddress((void**)&inv_p, g_inv);
    float* wat_p; cudaGetSymbolAddress((void**)&wat_p, g_WaT);

    // 0) zero accumulators (agg is also re-zeroed by combine, but stay robust)
    {
        int n = NNODES * HID;
        zero_kernel<<<(n + 255) / 256, 256>>>(agg_p, n);
        zero_kernel<<<(NNODES + 255) / 256, 256>>>(deg_p, NNODES);
    }

    // 1) h = relu(x @ W1^T + b1)
    {
        dim3 grid(HID / BN, (NNODES + BM - 1) / BM);
        gemm_relu_kernel<<<grid, 256>>>(x, W1, b1, h_p, NNODES, HID, F_IN);
    }

    // 2) degree + inv
    deg_kernel<<<(E + 255) / 256, 256>>>(tgt, deg_p, E);
    inv_kernel<<<(NNODES + 255) / 256, 256>>>(deg_p, inv_p, NNODES);

    // 3) two propagation rounds
    {
        long long tot = (long long)E * 64;
        int sblocks = (int)((tot + 255) / 256);
        int n4 = NNODES * HID / 4;
        int cblocks = (n4 + 255) / 256;

        scatter_kernel<<<sblocks, 256>>>(h_p, src, tgt, agg_p, E);
        combine_kernel<<<cblocks, 256>>>(h_p, agg_p, inv_p, n4);
        scatter_kernel<<<sblocks, 256>>>(h_p, src, tgt, agg_p, E);
        combine_kernel<<<cblocks, 256>>>(h_p, agg_p, inv_p, n4);
    }

    // 4) out = relu(h @ W2^T + b2)  -> directly into d_out
    {
        dim3 grid(OUT_D / BN, (NNODES + BM - 1) / BM);
        gemm_relu_kernel<<<grid, 256>>>(h_p, W2, b2, out_ptr, NNODES, OUT_D, HID);
    }

    // 5) attention head
    transpose_wa1_kernel<<<(OUT_D * ATT_H + 255) / 256, 256>>>(Wa1, wat_p);
    attention_kernel<<<(NNODES * 32 + 255) / 256, 256>>>(out_ptr, wat_p, ba1, Wa2, ba2,
                                                         att_ptr, NNODES);
}

// round 3
// speedup vs baseline: 1.3658x; 1.3658x over previous
#include <cuda_runtime.h>
#include <math.h>

// ---------------- problem constants ----------------
#define NNODES   10000
#define F_IN     384
#define HID      256
#define OUT_D    128
#define ATT_H    64
#define EDGES_MAX 320000

// ---------------- scratch (device globals; no allocation allowed) ----------------
__device__ float g_h [NNODES * HID];
__device__ float g_h2[NNODES * HID];
__device__ float g_inv[NNODES];
__device__ int   g_cnt[NNODES];
__device__ int   g_off[NNODES + 1];
__device__ int   g_cur[NNODES];
__device__ int   g_srcs[EDGES_MAX];
__device__ float g_WaT[OUT_D * ATT_H];   // Wa1 transposed: [k][j] = Wa1[j][k]

// ---------------- zero int counters ----------------
__global__ void zero_int_kernel(int* __restrict__ p, int n) {
    int i = blockIdx.x * blockDim.x + threadIdx.x;
    if (i < n) p[i] = 0;
}

// ---------------- count in-degree (int atomics) ----------------
__global__ void count_kernel(const int* __restrict__ tgt, int* __restrict__ cnt, int E) {
    int e = blockIdx.x * blockDim.x + threadIdx.x;
    if (e < E) atomicAdd(&cnt[tgt[e]], 1);
}

// ---------------- single-block scan: exclusive offsets + cur copy + inv ----------------
__global__ __launch_bounds__(1024) void scan_kernel(
    const int* __restrict__ cnt, int* __restrict__ off, int* __restrict__ cur,
    float* __restrict__ inv)
{
    __shared__ int s[1024];
    __shared__ int carry;
    int tid = threadIdx.x;
    if (tid == 0) carry = 0;
    __syncthreads();
    for (int base = 0; base < NNODES; base += 1024) {
        int i = base + tid;
        int v = (i < NNODES) ? cnt[i] : 0;
        s[tid] = v;
        __syncthreads();
#pragma unroll
        for (int d = 1; d < 1024; d <<= 1) {
            int t = (tid >= d) ? s[tid - d] : 0;
            __syncthreads();
            s[tid] += t;
            __syncthreads();
        }
        int excl = s[tid] - v + carry;
        if (i < NNODES) {
            off[i] = excl;
            cur[i] = excl;
            inv[i] = 1.0f / ((float)v + 1.0f);
        }
        __syncthreads();
        if (tid == 1023) carry += s[1023];
        __syncthreads();
    }
    if (tid == 0) off[NNODES] = carry;
}

// ---------------- fill CSR buckets ----------------
__global__ void fill_kernel(const int* __restrict__ src, const int* __restrict__ tgt,
                            int* __restrict__ cur, int* __restrict__ srcs, int E)
{
    int e = blockIdx.x * blockDim.x + threadIdx.x;
    if (e >= E) return;
    int t = tgt[e];
    int p = atomicAdd(&cur[t], 1);
    srcs[p] = src[e];
}

// ---------------- fused gather + combine ----------------
// 64 threads per node (float4 per thread over HID=256), 4 nodes per 256-thread block.
// hout[t] = 0.7*hin[t] + 0.3*inv[t]*sum_{s in N(t)} hin[s]
__global__ __launch_bounds__(256) void gather_combine_kernel(
    const float* __restrict__ hin, float* __restrict__ hout,
    const int* __restrict__ off, const int* __restrict__ srcs,
    const float* __restrict__ inv)
{
    int node = blockIdx.x * 4 + (threadIdx.x >> 6);
    if (node >= NNODES) return;
    int c = (threadIdx.x & 63) << 2;

    int beg = off[node];
    int end = off[node + 1];

    float4 acc = make_float4(0.f, 0.f, 0.f, 0.f);
    int i = beg;
    // 4-way unroll for MLP against L2 latency
    for (; i + 4 <= end; i += 4) {
        int s0 = __ldg(srcs + i);
        int s1 = __ldg(srcs + i + 1);
        int s2 = __ldg(srcs + i + 2);
        int s3 = __ldg(srcs + i + 3);
        float4 v0 = *reinterpret_cast<const float4*>(hin + (size_t)s0 * HID + c);
        float4 v1 = *reinterpret_cast<const float4*>(hin + (size_t)s1 * HID + c);
        float4 v2 = *reinterpret_cast<const float4*>(hin + (size_t)s2 * HID + c);
        float4 v3 = *reinterpret_cast<const float4*>(hin + (size_t)s3 * HID + c);
        acc.x += (v0.x + v1.x) + (v2.x + v3.x);
        acc.y += (v0.y + v1.y) + (v2.y + v3.y);
        acc.z += (v0.z + v1.z) + (v2.z + v3.z);
        acc.w += (v0.w + v1.w) + (v2.w + v3.w);
    }
    for (; i < end; i++) {
        int s0 = __ldg(srcs + i);
        float4 v0 = *reinterpret_cast<const float4*>(hin + (size_t)s0 * HID + c);
        acc.x += v0.x; acc.y += v0.y; acc.z += v0.z; acc.w += v0.w;
    }

    float sc = 0.3f * inv[node];
    float4 hv = *reinterpret_cast<const float4*>(hin + (size_t)node * HID + c);
    hv.x = 0.7f * hv.x + sc * acc.x;
    hv.y = 0.7f * hv.y + sc * acc.y;
    hv.z = 0.7f * hv.z + sc * acc.z;
    hv.w = 0.7f * hv.w + sc * acc.w;
    *reinterpret_cast<float4*>(hout + (size_t)node * HID + c) = hv;
}

// ---------------- fp32 GEMM: C[M,N] = relu(A[M,K] @ B[N,K]^T + bias[N]) ----------------
#define BM 128
#define BN 64
#define BKK 16
#define TM 8
#define TN 4

__global__ __launch_bounds__(256) void gemm_relu_kernel(
    const float* __restrict__ A, const float* __restrict__ B,
    const float* __restrict__ bias, float* __restrict__ C,
    int M, int N, int K)
{
    __shared__ float As[BKK][BM + 4];
    __shared__ float Bs[BKK][BN + 4];

    const int n0 = blockIdx.x * BN;
    const int m0 = blockIdx.y * BM;
    const int tid = threadIdx.x;
    const int tx = tid & 15;    // n-dir, TN=4 -> 64
    const int ty = tid >> 4;    // m-dir, TM=8 -> 128

    float acc[TM][TN];
#pragma unroll
    for (int i = 0; i < TM; i++)
#pragma unroll
        for (int j = 0; j < TN; j++) acc[i][j] = 0.0f;

    for (int k0 = 0; k0 < K; k0 += BKK) {
#pragma unroll
        for (int it = 0; it < (BM * BKK) / 256; it++) {
            int t = tid + it * 256;
            int m = t / BKK, k = t % BKK;
            int gm = m0 + m;
            As[k][m] = (gm < M) ? A[(size_t)gm * K + k0 + k] : 0.0f;
        }
#pragma unroll
        for (int it = 0; it < (BN * BKK) / 256; it++) {
            int t = tid + it * 256;
            int n = t / BKK, k = t % BKK;
            Bs[k][n] = B[(size_t)(n0 + n) * K + k0 + k];
        }
        __syncthreads();

#pragma unroll
        for (int k = 0; k < BKK; k++) {
            float a[TM], b[TN];
#pragma unroll
            for (int i = 0; i < TM; i++) a[i] = As[k][ty * TM + i];
#pragma unroll
            for (int j = 0; j < TN; j++) b[j] = Bs[k][tx * TN + j];
#pragma unroll
            for (int i = 0; i < TM; i++)
#pragma unroll
                for (int j = 0; j < TN; j++) acc[i][j] = fmaf(a[i], b[j], acc[i][j]);
        }
        __syncthreads();
    }

#pragma unroll
    for (int i = 0; i < TM; i++) {
        int m = m0 + ty * TM + i;
        if (m >= M) continue;
#pragma unroll
        for (int j = 0; j < TN; j++) {
            int n = n0 + tx * TN + j;
            float v = acc[i][j] + bias[n];
            C[(size_t)m * N + n] = v > 0.0f ? v : 0.0f;
        }
    }
}

// ---------------- transpose Wa1 (64x128) -> WaT (128x64) ----------------
__global__ void transpose_wa1_kernel(const float* __restrict__ Wa1, float* __restrict__ WaT) {
    int idx = blockIdx.x * blockDim.x + threadIdx.x;
    if (idx >= OUT_D * ATT_H) return;
    int k = idx / ATT_H;
    int j = idx % ATT_H;
    WaT[idx] = Wa1[j * OUT_D + k];
}

// ---------------- attention: warp per node ----------------
__global__ __launch_bounds__(256) void attention_kernel(
    const float* __restrict__ out, const float* __restrict__ WaT,
    const float* __restrict__ ba1, const float* __restrict__ Wa2,
    const float* __restrict__ ba2, float* __restrict__ att, int N)
{
    int warp = (blockIdx.x * blockDim.x + threadIdx.x) >> 5;
    int lane = threadIdx.x & 31;
    if (warp >= N) return;
    const float* o = out + (size_t)warp * OUT_D;
    float acc0 = ba1[lane];
    float acc1 = ba1[lane + 32];
#pragma unroll 4
    for (int k = 0; k < OUT_D; k++) {
        float ov = __ldg(o + k);
        acc0 = fmaf(WaT[k * ATT_H + lane],      ov, acc0);
        acc1 = fmaf(WaT[k * ATT_H + lane + 32], ov, acc1);
    }
    acc0 = fmaxf(acc0, 0.0f) * Wa2[lane];
    acc1 = fmaxf(acc1, 0.0f) * Wa2[lane + 32];
    float s = acc0 + acc1;
#pragma unroll
    for (int off = 16; off; off >>= 1) s += __shfl_xor_sync(0xffffffffu, s, off);
    if (lane == 0) att[warp] = 1.0f / (1.0f + expf(-(s + ba2[0])));
}

// ---------------- launch ----------------
extern "C" void kernel_launch(void* const* d_in, const int* in_sizes, int n_in,
                              void* d_out, int out_size)
{
    const float* x    = (const float*)d_in[0];
    const int*   ei   = (const int*)d_in[1];     // (2, E) int32: [src | tgt]
    const float* W1   = (const float*)d_in[2];
    const float* b1   = (const float*)d_in[3];
    const float* W2   = (const float*)d_in[4];
    const float* b2   = (const float*)d_in[5];
    const float* Wa1  = (const float*)d_in[6];
    const float* ba1  = (const float*)d_in[7];
    const float* Wa2  = (const float*)d_in[8];
    const float* ba2  = (const float*)d_in[9];

    const int E = in_sizes[1] / 2;
    const int* src = ei;
    const int* tgt = ei + E;

    float* out_ptr = (float*)d_out;                        // (N, 128)
    float* att_ptr = out_ptr + (size_t)NNODES * OUT_D;     // (N, 1)

    float* h_p;    cudaGetSymbolAddress((void**)&h_p,    g_h);
    float* h2_p;   cudaGetSymbolAddress((void**)&h2_p,   g_h2);
    float* inv_p;  cudaGetSymbolAddress((void**)&inv_p,  g_inv);
    int*   cnt_p;  cudaGetSymbolAddress((void**)&cnt_p,  g_cnt);
    int*   off_p;  cudaGetSymbolAddress((void**)&off_p,  g_off);
    int*   cur_p;  cudaGetSymbolAddress((void**)&cur_p,  g_cur);
    int*   srcs_p; cudaGetSymbolAddress((void**)&srcs_p, g_srcs);
    float* wat_p;  cudaGetSymbolAddress((void**)&wat_p,  g_WaT);

    // --- CSR build (overlaps conceptually with GEMM1 in the graph's stream order) ---
    zero_int_kernel<<<(NNODES + 255) / 256, 256>>>(cnt_p, NNODES);
    count_kernel<<<(E + 255) / 256, 256>>>(tgt, cnt_p, E);
    scan_kernel<<<1, 1024>>>(cnt_p, off_p, cur_p, inv_p);
    fill_kernel<<<(E + 255) / 256, 256>>>(src, tgt, cur_p, srcs_p, E);

    // --- h = relu(x @ W1^T + b1) ---
    {
        dim3 grid(HID / BN, (NNODES + BM - 1) / BM);
        gemm_relu_kernel<<<grid, 256>>>(x, W1, b1, h_p, NNODES, HID, F_IN);
    }

    // --- two propagation rounds (ping-pong h <-> h2) ---
    {
        int gblocks = (NNODES + 3) / 4;
        gather_combine_kernel<<<gblocks, 256>>>(h_p,  h2_p, off_p, srcs_p, inv_p);
        gather_combine_kernel<<<gblocks, 256>>>(h2_p, h_p,  off_p, srcs_p, inv_p);
    }

    // --- out = relu(h @ W2^T + b2) -> directly into d_out ---
    {
        dim3 grid(OUT_D / BN, (NNODES + BM - 1) / BM);
        gemm_relu_kernel<<<grid, 256>>>(h_p, W2, b2, out_ptr, NNODES, OUT_D, HID);
    }

    // --- attention head ---
    transpose_wa1_kernel<<<(OUT_D * ATT_H + 255) / 256, 256>>>(Wa1, wat_p);
    attention_kernel<<<(NNODES * 32 + 255) / 256, 256>>>(out_ptr, wat_p, ba1, Wa2, ba2,
                                                         att_ptr, NNODES);
}

// round 4
// speedup vs baseline: 2.1307x; 1.5601x over previous
#include <cuda_runtime.h>
#include <math.h>
#include <stdint.h>

// ---------------- problem constants ----------------
#define NNODES   10000
#define F_IN     384
#define HID      256
#define OUT_D    128
#define ATT_H    64
#define EDGES_MAX 320000

// ---------------- scratch (device globals; no allocation allowed) ----------------
__device__ float g_h [NNODES * HID];
__device__ float g_h2[NNODES * HID];
__device__ float g_inv[NNODES];
__device__ int   g_cnt[NNODES];
__device__ int   g_off[NNODES + 1];
__device__ int   g_cur[NNODES];
__device__ int   g_srcs[EDGES_MAX];
__device__ float g_WaT[OUT_D * ATT_H];   // Wa1 transposed: [k][j] = Wa1[j][k]

// ---------------- zero int counters ----------------
__global__ void zero_int_kernel(int* __restrict__ p, int n) {
    int i = blockIdx.x * blockDim.x + threadIdx.x;
    if (i < n) p[i] = 0;
}

// ---------------- count in-degree (int atomics) ----------------
__global__ void count_kernel(const int* __restrict__ tgt, int* __restrict__ cnt, int E) {
    int e = blockIdx.x * blockDim.x + threadIdx.x;
    if (e < E) atomicAdd(&cnt[tgt[e]], 1);
}

// ---------------- fast single-block scan (shfl 3-level), 10 elems/thread ----------------
__global__ __launch_bounds__(1024) void scan_kernel(
    const int* __restrict__ cnt, int* __restrict__ off, int* __restrict__ cur,
    float* __restrict__ inv)
{
    __shared__ int warp_sums[32];
    const int tid  = threadIdx.x;
    const int lane = tid & 31;
    const int warp = tid >> 5;
    const int base = tid * 10;

    int v[10];
    int sum = 0;
#pragma unroll
    for (int i = 0; i < 10; i++) {
        int idx = base + i;
        v[i] = (idx < NNODES) ? cnt[idx] : 0;
        sum += v[i];
    }
    // warp inclusive scan of per-thread sums
    int s = sum;
#pragma unroll
    for (int d = 1; d < 32; d <<= 1) {
        int t = __shfl_up_sync(0xffffffffu, s, d);
        if (lane >= d) s += t;
    }
    if (lane == 31) warp_sums[warp] = s;
    __syncthreads();
    if (warp == 0) {
        int ws = warp_sums[lane];
#pragma unroll
        for (int d = 1; d < 32; d <<= 1) {
            int t = __shfl_up_sync(0xffffffffu, ws, d);
            if (lane >= d) ws += t;
        }
        warp_sums[lane] = ws;
    }
    __syncthreads();
    int excl = s - sum + (warp ? warp_sums[warp - 1] : 0);
#pragma unroll
    for (int i = 0; i < 10; i++) {
        int idx = base + i;
        if (idx < NNODES) {
            off[idx] = excl;
            cur[idx] = excl;
            inv[idx] = 1.0f / ((float)v[i] + 1.0f);
            excl += v[i];
        }
    }
    if (tid == 1023) off[NNODES] = excl;   // == total E
}

// ---------------- fill CSR buckets ----------------
__global__ void fill_kernel(const int* __restrict__ src, const int* __restrict__ tgt,
                            int* __restrict__ cur, int* __restrict__ srcs, int E)
{
    int e = blockIdx.x * blockDim.x + threadIdx.x;
    if (e >= E) return;
    int t = tgt[e];
    int p = atomicAdd(&cur[t], 1);
    srcs[p] = src[e];
}

// ---------------- fused gather + combine ----------------
__global__ __launch_bounds__(256) void gather_combine_kernel(
    const float* __restrict__ hin, float* __restrict__ hout,
    const int* __restrict__ off, const int* __restrict__ srcs,
    const float* __restrict__ inv)
{
    int node = blockIdx.x * 4 + (threadIdx.x >> 6);
    if (node >= NNODES) return;
    int c = (threadIdx.x & 63) << 2;

    int beg = off[node];
    int end = off[node + 1];

    float4 acc = make_float4(0.f, 0.f, 0.f, 0.f);
    int i = beg;
    for (; i + 4 <= end; i += 4) {
        int s0 = __ldg(srcs + i);
        int s1 = __ldg(srcs + i + 1);
        int s2 = __ldg(srcs + i + 2);
        int s3 = __ldg(srcs + i + 3);
        float4 v0 = *reinterpret_cast<const float4*>(hin + (size_t)s0 * HID + c);
        float4 v1 = *reinterpret_cast<const float4*>(hin + (size_t)s1 * HID + c);
        float4 v2 = *reinterpret_cast<const float4*>(hin + (size_t)s2 * HID + c);
        float4 v3 = *reinterpret_cast<const float4*>(hin + (size_t)s3 * HID + c);
        acc.x += (v0.x + v1.x) + (v2.x + v3.x);
        acc.y += (v0.y + v1.y) + (v2.y + v3.y);
        acc.z += (v0.z + v1.z) + (v2.z + v3.z);
        acc.w += (v0.w + v1.w) + (v2.w + v3.w);
    }
    for (; i < end; i++) {
        int s0 = __ldg(srcs + i);
        float4 v0 = *reinterpret_cast<const float4*>(hin + (size_t)s0 * HID + c);
        acc.x += v0.x; acc.y += v0.y; acc.z += v0.z; acc.w += v0.w;
    }

    float sc = 0.3f * inv[node];
    float4 hv = *reinterpret_cast<const float4*>(hin + (size_t)node * HID + c);
    hv.x = 0.7f * hv.x + sc * acc.x;
    hv.y = 0.7f * hv.y + sc * acc.y;
    hv.z = 0.7f * hv.z + sc * acc.z;
    hv.w = 0.7f * hv.w + sc * acc.w;
    *reinterpret_cast<float4*>(hout + (size_t)node * HID + c) = hv;
}

// ---------------- tf32 tensor-core GEMM: C = relu(A[M,K] @ B[N,K]^T + bias) ----------------
// Block 256 thr = 8 warps (4m x 2n). Block tile 128x64, warp tile 32x32, k-step 8.
#define GBM 128
#define GBN 64
#define GBK 32
#define SKA 36   // padded smem row stride (words): bank = 4*row + col, conflict-free

__device__ __forceinline__ uint32_t f2tf32(float x) {
    uint32_t r;
    asm("cvt.rna.tf32.f32 %0, %1;" : "=r"(r) : "f"(x));
    return r;
}

__device__ __forceinline__ void mma_tf32(float* c, const uint32_t* a, const uint32_t* b) {
    asm volatile(
        "mma.sync.aligned.m16n8k8.row.col.f32.tf32.tf32.f32 "
        "{%0,%1,%2,%3}, {%4,%5,%6,%7}, {%8,%9}, {%0,%1,%2,%3};"
        : "+f"(c[0]), "+f"(c[1]), "+f"(c[2]), "+f"(c[3])
        : "r"(a[0]), "r"(a[1]), "r"(a[2]), "r"(a[3]), "r"(b[0]), "r"(b[1]));
}

__global__ __launch_bounds__(256) void gemm_tf32_relu_kernel(
    const float* __restrict__ A, const float* __restrict__ B,
    const float* __restrict__ bias, float* __restrict__ C,
    int M, int N, int K)
{
    __shared__ uint32_t As[GBM][SKA];
    __shared__ uint32_t Bs[GBN][SKA];

    const int tid  = threadIdx.x;
    const int lane = tid & 31;
    const int warp = tid >> 5;
    const int wm = warp >> 1;     // 0..3
    const int wn = warp & 1;      // 0..1
    const int g   = lane >> 2;    // group 0..7
    const int tig = lane & 3;     // 0..3
    const int m0 = blockIdx.y * GBM;
    const int n0 = blockIdx.x * GBN;

    float acc[2][4][4];
#pragma unroll
    for (int mm = 0; mm < 2; mm++)
#pragma unroll
        for (int nn = 0; nn < 4; nn++)
#pragma unroll
            for (int q = 0; q < 4; q++) acc[mm][nn][q] = 0.0f;

    for (int k0 = 0; k0 < K; k0 += GBK) {
        // A tile: 128x32 floats = 1024 float4, 4 per thread
#pragma unroll
        for (int it = 0; it < 4; it++) {
            int idx = tid + it * 256;
            int r = idx >> 3, c4 = (idx & 7) << 2;
            int gm = m0 + r;
            float4 v = (gm < M) ? *reinterpret_cast<const float4*>(A + (size_t)gm * K + k0 + c4)
                                : make_float4(0.f, 0.f, 0.f, 0.f);
            As[r][c4 + 0] = f2tf32(v.x);
            As[r][c4 + 1] = f2tf32(v.y);
            As[r][c4 + 2] = f2tf32(v.z);
            As[r][c4 + 3] = f2tf32(v.w);
        }
        // B tile: 64x32 floats = 512 float4, 2 per thread (N always multiple of 64)
#pragma unroll
        for (int it = 0; it < 2; it++) {
            int idx = tid + it * 256;
            int r = idx >> 3, c4 = (idx & 7) << 2;
            float4 v = *reinterpret_cast<const float4*>(B + (size_t)(n0 + r) * K + k0 + c4);
            Bs[r][c4 + 0] = f2tf32(v.x);
            Bs[r][c4 + 1] = f2tf32(v.y);
            Bs[r][c4 + 2] = f2tf32(v.z);
            Bs[r][c4 + 3] = f2tf32(v.w);
        }
        __syncthreads();

#pragma unroll
        for (int kk = 0; kk < GBK; kk += 8) {
            uint32_t af[2][4];
#pragma unroll
            for (int mm = 0; mm < 2; mm++) {
                int row = wm * 32 + mm * 16 + g;
                af[mm][0] = As[row][kk + tig];
                af[mm][1] = As[row + 8][kk + tig];
                af[mm][2] = As[row][kk + tig + 4];
                af[mm][3] = As[row + 8][kk + tig + 4];
            }
            uint32_t bf[4][2];
#pragma unroll
            for (int nn = 0; nn < 4; nn++) {
                int col = wn * 32 + nn * 8 + g;
                bf[nn][0] = Bs[col][kk + tig];
                bf[nn][1] = Bs[col][kk + tig + 4];
            }
#pragma unroll
            for (int mm = 0; mm < 2; mm++)
#pragma unroll
                for (int nn = 0; nn < 4; nn++)
                    mma_tf32(acc[mm][nn], af[mm], bf[nn]);
        }
        __syncthreads();
    }

    // epilogue: bias + relu
#pragma unroll
    for (int mm = 0; mm < 2; mm++) {
        int r0 = m0 + wm * 32 + mm * 16 + g;
#pragma unroll
        for (int nn = 0; nn < 4; nn++) {
            int col = n0 + wn * 32 + nn * 8 + tig * 2;
            float b0 = bias[col], b1 = bias[col + 1];
            if (r0 < M) {
                float v0 = acc[mm][nn][0] + b0;
                float v1 = acc[mm][nn][1] + b1;
                C[(size_t)r0 * N + col]     = v0 > 0.f ? v0 : 0.f;
                C[(size_t)r0 * N + col + 1] = v1 > 0.f ? v1 : 0.f;
            }
            if (r0 + 8 < M) {
                float v2 = acc[mm][nn][2] + b0;
                float v3 = acc[mm][nn][3] + b1;
                C[(size_t)(r0 + 8) * N + col]     = v2 > 0.f ? v2 : 0.f;
                C[(size_t)(r0 + 8) * N + col + 1] = v3 > 0.f ? v3 : 0.f;
            }
        }
    }
}

// ---------------- transpose Wa1 (64x128) -> WaT (128x64) ----------------
__global__ void transpose_wa1_kernel(const float* __restrict__ Wa1, float* __restrict__ WaT) {
    int idx = blockIdx.x * blockDim.x + threadIdx.x;
    if (idx >= OUT_D * ATT_H) return;
    int k = idx / ATT_H;
    int j = idx % ATT_H;
    WaT[idx] = Wa1[j * OUT_D + k];
}

// ---------------- attention: warp per node ----------------
__global__ __launch_bounds__(256) void attention_kernel(
    const float* __restrict__ out, const float* __restrict__ WaT,
    const float* __restrict__ ba1, const float* __restrict__ Wa2,
    const float* __restrict__ ba2, float* __restrict__ att, int N)
{
    int warp = (blockIdx.x * blockDim.x + threadIdx.x) >> 5;
    int lane = threadIdx.x & 31;
    if (warp >= N) return;
    const float* o = out + (size_t)warp * OUT_D;
    float acc0 = ba1[lane];
    float acc1 = ba1[lane + 32];
#pragma unroll 4
    for (int k = 0; k < OUT_D; k++) {
        float ov = __ldg(o + k);
        acc0 = fmaf(WaT[k * ATT_H + lane],      ov, acc0);
        acc1 = fmaf(WaT[k * ATT_H + lane + 32], ov, acc1);
    }
    acc0 = fmaxf(acc0, 0.0f) * Wa2[lane];
    acc1 = fmaxf(acc1, 0.0f) * Wa2[lane + 32];
    float s = acc0 + acc1;
#pragma unroll
    for (int off = 16; off; off >>= 1) s += __shfl_xor_sync(0xffffffffu, s, off);
    if (lane == 0) att[warp] = 1.0f / (1.0f + expf(-(s + ba2[0])));
}

// ---------------- launch ----------------
extern "C" void kernel_launch(void* const* d_in, const int* in_sizes, int n_in,
                              void* d_out, int out_size)
{
    const float* x    = (const float*)d_in[0];
    const int*   ei   = (const int*)d_in[1];     // (2, E) int32: [src | tgt]
    const float* W1   = (const float*)d_in[2];
    const float* b1   = (const float*)d_in[3];
    const float* W2   = (const float*)d_in[4];
    const float* b2   = (const float*)d_in[5];
    const float* Wa1  = (const float*)d_in[6];
    const float* ba1  = (const float*)d_in[7];
    const float* Wa2  = (const float*)d_in[8];
    const float* ba2  = (const float*)d_in[9];

    const int E = in_sizes[1] / 2;
    const int* src = ei;
    const int* tgt = ei + E;

    float* out_ptr = (float*)d_out;                        // (N, 128)
    float* att_ptr = out_ptr + (size_t)NNODES * OUT_D;     // (N, 1)

    float* h_p;    cudaGetSymbolAddress((void**)&h_p,    g_h);
    float* h2_p;   cudaGetSymbolAddress((void**)&h2_p,   g_h2);
    float* inv_p;  cudaGetSymbolAddress((void**)&inv_p,  g_inv);
    int*   cnt_p;  cudaGetSymbolAddress((void**)&cnt_p,  g_cnt);
    int*   off_p;  cudaGetSymbolAddress((void**)&off_p,  g_off);
    int*   cur_p;  cudaGetSymbolAddress((void**)&cur_p,  g_cur);
    int*   srcs_p; cudaGetSymbolAddress((void**)&srcs_p, g_srcs);
    float* wat_p;  cudaGetSymbolAddress((void**)&wat_p,  g_WaT);

    // --- CSR build ---
    zero_int_kernel<<<(NNODES + 255) / 256, 256>>>(cnt_p, NNODES);
    count_kernel<<<(E + 255) / 256, 256>>>(tgt, cnt_p, E);
    scan_kernel<<<1, 1024>>>(cnt_p, off_p, cur_p, inv_p);
    fill_kernel<<<(E + 255) / 256, 256>>>(src, tgt, cur_p, srcs_p, E);

    // --- h = relu(x @ W1^T + b1)  (tf32 tensor cores) ---
    {
        dim3 grid(HID / GBN, (NNODES + GBM - 1) / GBM);
        gemm_tf32_relu_kernel<<<grid, 256>>>(x, W1, b1, h_p, NNODES, HID, F_IN);
    }

    // --- two propagation rounds (ping-pong h <-> h2) ---
    {
        int gblocks = (NNODES + 3) / 4;
        gather_combine_kernel<<<gblocks, 256>>>(h_p,  h2_p, off_p, srcs_p, inv_p);
        gather_combine_kernel<<<gblocks, 256>>>(h2_p, h_p,  off_p, srcs_p, inv_p);
    }

    // --- out = relu(h @ W2^T + b2) -> directly into d_out (tf32) ---
    {
        dim3 grid(OUT_D / GBN, (NNODES + GBM - 1) / GBM);
        gemm_tf32_relu_kernel<<<grid, 256>>>(h_p, W2, b2, out_ptr, NNODES, OUT_D, HID);
    }

    // --- attention head ---
    transpose_wa1_kernel<<<(OUT_D * ATT_H + 255) / 256, 256>>>(Wa1, wat_p);
    attention_kernel<<<(NNODES * 32 + 255) / 256, 256>>>(out_ptr, wat_p, ba1, Wa2, ba2,
                                                         att_ptr, NNODES);
}

// round 5
// speedup vs baseline: 2.3943x; 1.1237x over previous
#include <cuda_runtime.h>
#include <math.h>
#include <stdint.h>

// ---------------- problem constants ----------------
#define NNODES   10000
#define F_IN     384
#define HID      256
#define OUT_D    128
#define ATT_H    64
#define EDGES_MAX 320000

// ---------------- scratch (device globals; no allocation allowed) ----------------
__device__ float g_h [NNODES * HID];
__device__ float g_h2[NNODES * HID];
__device__ float g_inv[NNODES];
__device__ int   g_cnt[NNODES];
__device__ int   g_off[NNODES + 1];
__device__ int   g_cur[NNODES];
__device__ int   g_srcs[EDGES_MAX];
__device__ float g_WaT[OUT_D * ATT_H];   // Wa1 transposed: [k][j] = Wa1[j][k]

// ---------------- zero int counters ----------------
__global__ void zero_int_kernel(int* __restrict__ p, int n) {
    int i = blockIdx.x * blockDim.x + threadIdx.x;
    if (i < n) p[i] = 0;
}

// ---------------- count in-degree, 4 edges/thread for atomic MLP ----------------
__global__ void count_kernel(const int* __restrict__ tgt, int* __restrict__ cnt, int E) {
    int i = (blockIdx.x * blockDim.x + threadIdx.x) * 4;
    if (i + 4 <= E) {
        int t0 = tgt[i], t1 = tgt[i + 1], t2 = tgt[i + 2], t3 = tgt[i + 3];
        atomicAdd(&cnt[t0], 1);
        atomicAdd(&cnt[t1], 1);
        atomicAdd(&cnt[t2], 1);
        atomicAdd(&cnt[t3], 1);
    } else {
        for (; i < E; i++) atomicAdd(&cnt[tgt[i]], 1);
    }
}

// ---------------- fast single-block scan (shfl 3-level), 10 elems/thread ----------------
__global__ __launch_bounds__(1024) void scan_kernel(
    const int* __restrict__ cnt, int* __restrict__ off, int* __restrict__ cur,
    float* __restrict__ inv)
{
    __shared__ int warp_sums[32];
    const int tid  = threadIdx.x;
    const int lane = tid & 31;
    const int warp = tid >> 5;
    const int base = tid * 10;

    int v[10];
    int sum = 0;
#pragma unroll
    for (int i = 0; i < 10; i++) {
        int idx = base + i;
        v[i] = (idx < NNODES) ? cnt[idx] : 0;
        sum += v[i];
    }
    int s = sum;
#pragma unroll
    for (int d = 1; d < 32; d <<= 1) {
        int t = __shfl_up_sync(0xffffffffu, s, d);
        if (lane >= d) s += t;
    }
    if (lane == 31) warp_sums[warp] = s;
    __syncthreads();
    if (warp == 0) {
        int ws = warp_sums[lane];
#pragma unroll
        for (int d = 1; d < 32; d <<= 1) {
            int t = __shfl_up_sync(0xffffffffu, ws, d);
            if (lane >= d) ws += t;
        }
        warp_sums[lane] = ws;
    }
    __syncthreads();
    int excl = s - sum + (warp ? warp_sums[warp - 1] : 0);
#pragma unroll
    for (int i = 0; i < 10; i++) {
        int idx = base + i;
        if (idx < NNODES) {
            off[idx] = excl;
            cur[idx] = excl;
            inv[idx] = 1.0f / ((float)v[i] + 1.0f);
            excl += v[i];
        }
    }
    if (tid == 1023) off[NNODES] = excl;
}

// ---------------- fill CSR buckets, 4 edges/thread ----------------
__global__ void fill_kernel(const int* __restrict__ src, const int* __restrict__ tgt,
                            int* __restrict__ cur, int* __restrict__ srcs, int E)
{
    int i = (blockIdx.x * blockDim.x + threadIdx.x) * 4;
    if (i + 4 <= E) {
        int t0 = tgt[i], t1 = tgt[i + 1], t2 = tgt[i + 2], t3 = tgt[i + 3];
        int s0 = src[i], s1 = src[i + 1], s2 = src[i + 2], s3 = src[i + 3];
        int p0 = atomicAdd(&cur[t0], 1);
        int p1 = atomicAdd(&cur[t1], 1);
        int p2 = atomicAdd(&cur[t2], 1);
        int p3 = atomicAdd(&cur[t3], 1);
        srcs[p0] = s0;
        srcs[p1] = s1;
        srcs[p2] = s2;
        srcs[p3] = s3;
    } else {
        for (; i < E; i++) {
            int p = atomicAdd(&cur[tgt[i]], 1);
            srcs[p] = src[i];
        }
    }
}

// ---------------- fused gather + combine ----------------
__global__ __launch_bounds__(256) void gather_combine_kernel(
    const float* __restrict__ hin, float* __restrict__ hout,
    const int* __restrict__ off, const int* __restrict__ srcs,
    const float* __restrict__ inv)
{
    int node = blockIdx.x * 4 + (threadIdx.x >> 6);
    if (node >= NNODES) return;
    int c = (threadIdx.x & 63) << 2;

    int beg = off[node];
    int end = off[node + 1];

    float4 acc = make_float4(0.f, 0.f, 0.f, 0.f);
    int i = beg;
    for (; i + 4 <= end; i += 4) {
        int s0 = __ldg(srcs + i);
        int s1 = __ldg(srcs + i + 1);
        int s2 = __ldg(srcs + i + 2);
        int s3 = __ldg(srcs + i + 3);
        float4 v0 = *reinterpret_cast<const float4*>(hin + (size_t)s0 * HID + c);
        float4 v1 = *reinterpret_cast<const float4*>(hin + (size_t)s1 * HID + c);
        float4 v2 = *reinterpret_cast<const float4*>(hin + (size_t)s2 * HID + c);
        float4 v3 = *reinterpret_cast<const float4*>(hin + (size_t)s3 * HID + c);
        acc.x += (v0.x + v1.x) + (v2.x + v3.x);
        acc.y += (v0.y + v1.y) + (v2.y + v3.y);
        acc.z += (v0.z + v1.z) + (v2.z + v3.z);
        acc.w += (v0.w + v1.w) + (v2.w + v3.w);
    }
    for (; i < end; i++) {
        int s0 = __ldg(srcs + i);
        float4 v0 = *reinterpret_cast<const float4*>(hin + (size_t)s0 * HID + c);
        acc.x += v0.x; acc.y += v0.y; acc.z += v0.z; acc.w += v0.w;
    }

    float sc = 0.3f * inv[node];
    float4 hv = *reinterpret_cast<const float4*>(hin + (size_t)node * HID + c);
    hv.x = 0.7f * hv.x + sc * acc.x;
    hv.y = 0.7f * hv.y + sc * acc.y;
    hv.z = 0.7f * hv.z + sc * acc.z;
    hv.w = 0.7f * hv.w + sc * acc.w;
    *reinterpret_cast<float4*>(hout + (size_t)node * HID + c) = hv;
}

// ---------------- tf32 tensor-core GEMM: C = relu(A[M,K] @ B[N,K]^T + bias) ----------------
#define GBM 128
#define GBN 64
#define GBK 32
#define SKA 36

__device__ __forceinline__ uint32_t f2tf32(float x) {
    uint32_t r;
    asm("cvt.rna.tf32.f32 %0, %1;" : "=r"(r) : "f"(x));
    return r;
}

__device__ __forceinline__ void mma_tf32(float* c, const uint32_t* a, const uint32_t* b) {
    asm volatile(
        "mma.sync.aligned.m16n8k8.row.col.f32.tf32.tf32.f32 "
        "{%0,%1,%2,%3}, {%4,%5,%6,%7}, {%8,%9}, {%0,%1,%2,%3};"
        : "+f"(c[0]), "+f"(c[1]), "+f"(c[2]), "+f"(c[3])
        : "r"(a[0]), "r"(a[1]), "r"(a[2]), "r"(a[3]), "r"(b[0]), "r"(b[1]));
}

__global__ __launch_bounds__(256) void gemm_tf32_relu_kernel(
    const float* __restrict__ A, const float* __restrict__ B,
    const float* __restrict__ bias, float* __restrict__ C,
    int M, int N, int K)
{
    __shared__ uint32_t As[GBM][SKA];
    __shared__ uint32_t Bs[GBN][SKA];

    const int tid  = threadIdx.x;
    const int lane = tid & 31;
    const int warp = tid >> 5;
    const int wm = warp >> 1;
    const int wn = warp & 1;
    const int g   = lane >> 2;
    const int tig = lane & 3;
    const int m0 = blockIdx.y * GBM;
    const int n0 = blockIdx.x * GBN;

    float acc[2][4][4];
#pragma unroll
    for (int mm = 0; mm < 2; mm++)
#pragma unroll
        for (int nn = 0; nn < 4; nn++)
#pragma unroll
            for (int q = 0; q < 4; q++) acc[mm][nn][q] = 0.0f;

    for (int k0 = 0; k0 < K; k0 += GBK) {
#pragma unroll
        for (int it = 0; it < 4; it++) {
            int idx = tid + it * 256;
            int r = idx >> 3, c4 = (idx & 7) << 2;
            int gm = m0 + r;
            float4 v = (gm < M) ? *reinterpret_cast<const float4*>(A + (size_t)gm * K + k0 + c4)
                                : make_float4(0.f, 0.f, 0.f, 0.f);
            As[r][c4 + 0] = f2tf32(v.x);
            As[r][c4 + 1] = f2tf32(v.y);
            As[r][c4 + 2] = f2tf32(v.z);
            As[r][c4 + 3] = f2tf32(v.w);
        }
#pragma unroll
        for (int it = 0; it < 2; it++) {
            int idx = tid + it * 256;
            int r = idx >> 3, c4 = (idx & 7) << 2;
            float4 v = *reinterpret_cast<const float4*>(B + (size_t)(n0 + r) * K + k0 + c4);
            Bs[r][c4 + 0] = f2tf32(v.x);
            Bs[r][c4 + 1] = f2tf32(v.y);
            Bs[r][c4 + 2] = f2tf32(v.z);
            Bs[r][c4 + 3] = f2tf32(v.w);
        }
        __syncthreads();

#pragma unroll
        for (int kk = 0; kk < GBK; kk += 8) {
            uint32_t af[2][4];
#pragma unroll
            for (int mm = 0; mm < 2; mm++) {
                int row = wm * 32 + mm * 16 + g;
                af[mm][0] = As[row][kk + tig];
                af[mm][1] = As[row + 8][kk + tig];
                af[mm][2] = As[row][kk + tig + 4];
                af[mm][3] = As[row + 8][kk + tig + 4];
            }
            uint32_t bf[4][2];
#pragma unroll
            for (int nn = 0; nn < 4; nn++) {
                int col = wn * 32 + nn * 8 + g;
                bf[nn][0] = Bs[col][kk + tig];
                bf[nn][1] = Bs[col][kk + tig + 4];
            }
#pragma unroll
            for (int mm = 0; mm < 2; mm++)
#pragma unroll
                for (int nn = 0; nn < 4; nn++)
                    mma_tf32(acc[mm][nn], af[mm], bf[nn]);
        }
        __syncthreads();
    }

#pragma unroll
    for (int mm = 0; mm < 2; mm++) {
        int r0 = m0 + wm * 32 + mm * 16 + g;
#pragma unroll
        for (int nn = 0; nn < 4; nn++) {
            int col = n0 + wn * 32 + nn * 8 + tig * 2;
            float b0 = bias[col], b1 = bias[col + 1];
            if (r0 < M) {
                float v0 = acc[mm][nn][0] + b0;
                float v1 = acc[mm][nn][1] + b1;
                C[(size_t)r0 * N + col]     = v0 > 0.f ? v0 : 0.f;
                C[(size_t)r0 * N + col + 1] = v1 > 0.f ? v1 : 0.f;
            }
            if (r0 + 8 < M) {
                float v2 = acc[mm][nn][2] + b0;
                float v3 = acc[mm][nn][3] + b1;
                C[(size_t)(r0 + 8) * N + col]     = v2 > 0.f ? v2 : 0.f;
                C[(size_t)(r0 + 8) * N + col + 1] = v3 > 0.f ? v3 : 0.f;
            }
        }
    }
}

// ---------------- transpose Wa1 (64x128) -> WaT (128x64) ----------------
__global__ void transpose_wa1_kernel(const float* __restrict__ Wa1, float* __restrict__ WaT) {
    int idx = blockIdx.x * blockDim.x + threadIdx.x;
    if (idx >= OUT_D * ATT_H) return;
    int k = idx / ATT_H;
    int j = idx % ATT_H;
    WaT[idx] = Wa1[j * OUT_D + k];
}

// ---------------- attention: warp per node ----------------
__global__ __launch_bounds__(256) void attention_kernel(
    const float* __restrict__ out, const float* __restrict__ WaT,
    const float* __restrict__ ba1, const float* __restrict__ Wa2,
    const float* __restrict__ ba2, float* __restrict__ att, int N)
{
    int warp = (blockIdx.x * blockDim.x + threadIdx.x) >> 5;
    int lane = threadIdx.x & 31;
    if (warp >= N) return;
    const float* o = out + (size_t)warp * OUT_D;
    float acc0 = ba1[lane];
    float acc1 = ba1[lane + 32];
#pragma unroll 4
    for (int k = 0; k < OUT_D; k++) {
        float ov = __ldg(o + k);
        acc0 = fmaf(WaT[k * ATT_H + lane],      ov, acc0);
        acc1 = fmaf(WaT[k * ATT_H + lane + 32], ov, acc1);
    }
    acc0 = fmaxf(acc0, 0.0f) * Wa2[lane];
    acc1 = fmaxf(acc1, 0.0f) * Wa2[lane + 32];
    float s = acc0 + acc1;
#pragma unroll
    for (int off = 16; off; off >>= 1) s += __shfl_xor_sync(0xffffffffu, s, off);
    if (lane == 0) att[warp] = 1.0f / (1.0f + expf(-(s + ba2[0])));
}

// ---------------- launch ----------------
extern "C" void kernel_launch(void* const* d_in, const int* in_sizes, int n_in,
                              void* d_out, int out_size)
{
    const float* x    = (const float*)d_in[0];
    const int*   ei   = (const int*)d_in[1];     // (2, E) int32: [src | tgt]
    const float* W1   = (const float*)d_in[2];
    const float* b1   = (const float*)d_in[3];
    const float* W2   = (const float*)d_in[4];
    const float* b2   = (const float*)d_in[5];
    const float* Wa1  = (const float*)d_in[6];
    const float* ba1  = (const float*)d_in[7];
    const float* Wa2  = (const float*)d_in[8];
    const float* ba2  = (const float*)d_in[9];

    const int E = in_sizes[1] / 2;
    const int* src = ei;
    const int* tgt = ei + E;

    float* out_ptr = (float*)d_out;                        // (N, 128)
    float* att_ptr = out_ptr + (size_t)NNODES * OUT_D;     // (N, 1)

    float* h_p;    cudaGetSymbolAddress((void**)&h_p,    g_h);
    float* h2_p;   cudaGetSymbolAddress((void**)&h2_p,   g_h2);
    float* inv_p;  cudaGetSymbolAddress((void**)&inv_p,  g_inv);
    int*   cnt_p;  cudaGetSymbolAddress((void**)&cnt_p,  g_cnt);
    int*   off_p;  cudaGetSymbolAddress((void**)&off_p,  g_off);
    int*   cur_p;  cudaGetSymbolAddress((void**)&cur_p,  g_cur);
    int*   srcs_p; cudaGetSymbolAddress((void**)&srcs_p, g_srcs);
    float* wat_p;  cudaGetSymbolAddress((void**)&wat_p,  g_WaT);

    // --- fork a side stream for the CSR build + Wa1 transpose (independent of GEMM1) ---
    cudaStream_t side;
    cudaStreamCreateWithFlags(&side, cudaStreamNonBlocking);
    cudaEvent_t ev_fork, ev_csr;
    cudaEventCreateWithFlags(&ev_fork, cudaEventDisableTiming);
    cudaEventCreateWithFlags(&ev_csr,  cudaEventDisableTiming);

    cudaEventRecord(ev_fork, 0);
    cudaStreamWaitEvent(side, ev_fork, 0);

    // side branch: transpose + CSR build
    transpose_wa1_kernel<<<(OUT_D * ATT_H + 255) / 256, 256, 0, side>>>(Wa1, wat_p);
    zero_int_kernel<<<(NNODES + 255) / 256, 256, 0, side>>>(cnt_p, NNODES);
    count_kernel<<<(E / 4 + 255) / 256, 256, 0, side>>>(tgt, cnt_p, E);
    scan_kernel<<<1, 1024, 0, side>>>(cnt_p, off_p, cur_p, inv_p);
    fill_kernel<<<(E / 4 + 255) / 256, 256, 0, side>>>(src, tgt, cur_p, srcs_p, E);
    cudaEventRecord(ev_csr, side);

    // main branch: h = relu(x @ W1^T + b1)  (tf32 tensor cores)
    {
        dim3 grid(HID / GBN, (NNODES + GBM - 1) / GBM);
        gemm_tf32_relu_kernel<<<grid, 256>>>(x, W1, b1, h_p, NNODES, HID, F_IN);
    }

    // join: gathers need both GEMM1 (h) and the CSR
    cudaStreamWaitEvent(0, ev_csr, 0);

    // --- two propagation rounds (ping-pong h <-> h2) ---
    {
        int gblocks = (NNODES + 3) / 4;
        gather_combine_kernel<<<gblocks, 256>>>(h_p,  h2_p, off_p, srcs_p, inv_p);
        gather_combine_kernel<<<gblocks, 256>>>(h2_p, h_p,  off_p, srcs_p, inv_p);
    }

    // --- out = relu(h @ W2^T + b2) -> directly into d_out (tf32) ---
    {
        dim3 grid(OUT_D / GBN, (NNODES + GBM - 1) / GBM);
        gemm_tf32_relu_kernel<<<grid, 256>>>(h_p, W2, b2, out_ptr, NNODES, OUT_D, HID);
    }

    // --- attention head (WaT already built on side branch, joined above) ---
    attention_kernel<<<(NNODES * 32 + 255) / 256, 256>>>(out_ptr, wat_p, ba1, Wa2, ba2,
                                                         att_ptr, NNODES);

    cudaEventDestroy(ev_fork);
    cudaEventDestroy(ev_csr);
    cudaStreamDestroy(side);
}

// round 8
// speedup vs baseline: 2.5899x; 1.0817x over previous
#include <cuda_runtime.h>
#include <math.h>
#include <stdint.h>

// ---------------- problem constants ----------------
#define NNODES   10000
#define F_IN     384
#define HID      256
#define OUT_D    128
#define ATT_H    64
#define EDGES_MAX 320000

#define SCAN_BLOCKS 40
#define SCAN_TPB    256   // 40*256 = 10240 >= NNODES

// ---------------- scratch (device globals; no allocation allowed) ----------------
__device__ float g_h [NNODES * HID];
__device__ float g_h2[NNODES * HID];
__device__ float g_inv[NNODES];
__device__ int   g_cnt[NNODES];          // zero-init; re-zeroed by scan phase 3 each launch
__device__ int   g_off[NNODES + 1];
__device__ int   g_cur[NNODES];
__device__ int   g_bsum[SCAN_BLOCKS];
__device__ int   g_bofs[SCAN_BLOCKS];
__device__ int   g_srcs[EDGES_MAX];
__device__ float g_WaT[OUT_D * ATT_H];   // Wa1 transposed: [k][j] = Wa1[j][k]

// ---------------- count in-degree, 4 edges/thread for atomic MLP ----------------
__global__ void count_kernel(const int* __restrict__ tgt, int* __restrict__ cnt, int E) {
    int i = (blockIdx.x * blockDim.x + threadIdx.x) * 4;
    if (i + 4 <= E) {
        int t0 = tgt[i], t1 = tgt[i + 1], t2 = tgt[i + 2], t3 = tgt[i + 3];
        atomicAdd(&cnt[t0], 1);
        atomicAdd(&cnt[t1], 1);
        atomicAdd(&cnt[t2], 1);
        atomicAdd(&cnt[t3], 1);
    } else {
        for (; i < E; i++) atomicAdd(&cnt[tgt[i]], 1);
    }
}

// ---------------- scan phase 1: per-block chunk sums ----------------
__global__ __launch_bounds__(SCAN_TPB) void scan1_kernel(
    const int* __restrict__ cnt, int* __restrict__ bsum)
{
    __shared__ int wsum[SCAN_TPB / 32];
    int idx = blockIdx.x * SCAN_TPB + threadIdx.x;
    int v = (idx < NNODES) ? cnt[idx] : 0;
    int lane = threadIdx.x & 31;
    int warp = threadIdx.x >> 5;
#pragma unroll
    for (int d = 16; d; d >>= 1) v += __shfl_xor_sync(0xffffffffu, v, d);
    if (lane == 0) wsum[warp] = v;
    __syncthreads();
    if (threadIdx.x == 0) {
        int s = 0;
#pragma unroll
        for (int w = 0; w < SCAN_TPB / 32; w++) s += wsum[w];
        bsum[blockIdx.x] = s;
    }
}

// ---------------- scan phase 2: scan block sums (2 full warps), write off[N]=E ----------------
__global__ void scan2_kernel(const int* __restrict__ bsum, int* __restrict__ bofs,
                             int* __restrict__ off)
{
    int lane = threadIdx.x;                 // 64 threads >= SCAN_BLOCKS=40
    int v = (lane < SCAN_BLOCKS) ? bsum[lane] : 0;
    int lane32 = lane & 31;
    int half = lane >> 5;
    int s = v;
#pragma unroll
    for (int d = 1; d < 32; d <<= 1) {
        int t = __shfl_up_sync(0xffffffffu, s, d);
        if (lane32 >= d) s += t;
    }
    __shared__ int w0tot;
    if (lane == 31) w0tot = s;
    __syncthreads();
    int incl = s + (half ? w0tot : 0);
    if (lane < SCAN_BLOCKS) bofs[lane] = incl - v;   // exclusive
    if (lane == SCAN_BLOCKS - 1) off[NNODES] = incl; // total == E
}

// ---------------- scan phase 3: intra-chunk exclusive scan + outputs; re-zero cnt ----------------
__global__ __launch_bounds__(SCAN_TPB) void scan3_kernel(
    int* __restrict__ cnt, const int* __restrict__ bofs,
    int* __restrict__ off, int* __restrict__ cur, float* __restrict__ inv)
{
    __shared__ int wsum[SCAN_TPB / 32];
    int idx = blockIdx.x * SCAN_TPB + threadIdx.x;
    int lane = threadIdx.x & 31;
    int warp = threadIdx.x >> 5;
    int v = (idx < NNODES) ? cnt[idx] : 0;

    int s = v;
#pragma unroll
    for (int d = 1; d < 32; d <<= 1) {
        int t = __shfl_up_sync(0xffffffffu, s, d);
        if (lane >= d) s += t;
    }
    if (lane == 31) wsum[warp] = s;
    __syncthreads();
    // cross-warp scan: ALL 32 lanes of warp 0 participate in the shfl (upper lanes inert)
    if (warp == 0) {
        int ws = (lane < SCAN_TPB / 32) ? wsum[lane] : 0;
#pragma unroll
        for (int d = 1; d < SCAN_TPB / 32; d <<= 1) {
            int t = __shfl_up_sync(0xffffffffu, ws, d);
            if (lane >= d) ws += t;
        }
        if (lane < SCAN_TPB / 32) wsum[lane] = ws;
    }
    __syncthreads();
    int excl = s - v + (warp ? wsum[warp - 1] : 0) + bofs[blockIdx.x];
    if (idx < NNODES) {
        off[idx] = excl;
        cur[idx] = excl;
        inv[idx] = 1.0f / ((float)v + 1.0f);
        cnt[idx] = 0;   // restore invariant for next launch
    }
}

// ---------------- fill CSR buckets, 4 edges/thread ----------------
__global__ void fill_kernel(const int* __restrict__ src, const int* __restrict__ tgt,
                            int* __restrict__ cur, int* __restrict__ srcs, int E)
{
    int i = (blockIdx.x * blockDim.x + threadIdx.x) * 4;
    if (i + 4 <= E) {
        int t0 = tgt[i], t1 = tgt[i + 1], t2 = tgt[i + 2], t3 = tgt[i + 3];
        int s0 = src[i], s1 = src[i + 1], s2 = src[i + 2], s3 = src[i + 3];
        int p0 = atomicAdd(&cur[t0], 1);
        int p1 = atomicAdd(&cur[t1], 1);
        int p2 = atomicAdd(&cur[t2], 1);
        int p3 = atomicAdd(&cur[t3], 1);
        srcs[p0] = s0;
        srcs[p1] = s1;
        srcs[p2] = s2;
        srcs[p3] = s3;
    } else {
        for (; i < E; i++) {
            int p = atomicAdd(&cur[tgt[i]], 1);
            srcs[p] = src[i];
        }
    }
}

// ---------------- fused gather + combine ----------------
__global__ __launch_bounds__(256) void gather_combine_kernel(
    const float* __restrict__ hin, float* __restrict__ hout,
    const int* __restrict__ off, const int* __restrict__ srcs,
    const float* __restrict__ inv)
{
    int node = blockIdx.x * 4 + (threadIdx.x >> 6);
    if (node >= NNODES) return;
    int c = (threadIdx.x & 63) << 2;

    int beg = off[node];
    int end = off[node + 1];

    float4 acc = make_float4(0.f, 0.f, 0.f, 0.f);
    int i = beg;
    for (; i + 4 <= end; i += 4) {
        int s0 = __ldg(srcs + i);
        int s1 = __ldg(srcs + i + 1);
        int s2 = __ldg(srcs + i + 2);
        int s3 = __ldg(srcs + i + 3);
        float4 v0 = *reinterpret_cast<const float4*>(hin + (size_t)s0 * HID + c);
        float4 v1 = *reinterpret_cast<const float4*>(hin + (size_t)s1 * HID + c);
        float4 v2 = *reinterpret_cast<const float4*>(hin + (size_t)s2 * HID + c);
        float4 v3 = *reinterpret_cast<const float4*>(hin + (size_t)s3 * HID + c);
        acc.x += (v0.x + v1.x) + (v2.x + v3.x);
        acc.y += (v0.y + v1.y) + (v2.y + v3.y);
        acc.z += (v0.z + v1.z) + (v2.z + v3.z);
        acc.w += (v0.w + v1.w) + (v2.w + v3.w);
    }
    for (; i < end; i++) {
        int s0 = __ldg(srcs + i);
        float4 v0 = *reinterpret_cast<const float4*>(hin + (size_t)s0 * HID + c);
        acc.x += v0.x; acc.y += v0.y; acc.z += v0.z; acc.w += v0.w;
    }

    float sc = 0.3f * inv[node];
    float4 hv = *reinterpret_cast<const float4*>(hin + (size_t)node * HID + c);
    hv.x = 0.7f * hv.x + sc * acc.x;
    hv.y = 0.7f * hv.y + sc * acc.y;
    hv.z = 0.7f * hv.z + sc * acc.z;
    hv.w = 0.7f * hv.w + sc * acc.w;
    *reinterpret_cast<float4*>(hout + (size_t)node * HID + c) = hv;
}

// ---------------- tf32 tensor-core GEMM: C = relu(A[M,K] @ B[N,K]^T + bias) ----------------
#define GBM 128
#define GBN 64
#define GBK 32
#define SKA 36

__device__ __forceinline__ uint32_t f2tf32(float x) {
    uint32_t r;
    asm("cvt.rna.tf32.f32 %0, %1;" : "=r"(r) : "f"(x));
    return r;
}

__device__ __forceinline__ void mma_tf32(float* c, const uint32_t* a, const uint32_t* b) {
    asm volatile(
        "mma.sync.aligned.m16n8k8.row.col.f32.tf32.tf32.f32 "
        "{%0,%1,%2,%3}, {%4,%5,%6,%7}, {%8,%9}, {%0,%1,%2,%3};"
        : "+f"(c[0]), "+f"(c[1]), "+f"(c[2]), "+f"(c[3])
        : "r"(a[0]), "r"(a[1]), "r"(a[2]), "r"(a[3]), "r"(b[0]), "r"(b[1]));
}

__global__ __launch_bounds__(256) void gemm_tf32_relu_kernel(
    const float* __restrict__ A, const float* __restrict__ B,
    const float* __restrict__ bias, float* __restrict__ C,
    int M, int N, int K)
{
    __shared__ uint32_t As[GBM][SKA];
    __shared__ uint32_t Bs[GBN][SKA];

    const int tid  = threadIdx.x;
    const int lane = tid & 31;
    const int warp = tid >> 5;
    const int wm = warp >> 1;
    const int wn = warp & 1;
    const int g   = lane >> 2;
    const int tig = lane & 3;
    const int m0 = blockIdx.y * GBM;
    const int n0 = blockIdx.x * GBN;

    float acc[2][4][4];
#pragma unroll
    for (int mm = 0; mm < 2; mm++)
#pragma unroll
        for (int nn = 0; nn < 4; nn++)
#pragma unroll
            for (int q = 0; q < 4; q++) acc[mm][nn][q] = 0.0f;

    for (int k0 = 0; k0 < K; k0 += GBK) {
#pragma unroll
        for (int it = 0; it < 4; it++) {
            int idx = tid + it * 256;
            int r = idx >> 3, c4 = (idx & 7) << 2;
            int gm = m0 + r;
            float4 v = (gm < M) ? *reinterpret_cast<const float4*>(A + (size_t)gm * K + k0 + c4)
                                : make_float4(0.f, 0.f, 0.f, 0.f);
            As[r][c4 + 0] = f2tf32(v.x);
            As[r][c4 + 1] = f2tf32(v.y);
            As[r][c4 + 2] = f2tf32(v.z);
            As[r][c4 + 3] = f2tf32(v.w);
        }
#pragma unroll
        for (int it = 0; it < 2; it++) {
            int idx = tid + it * 256;
            int r = idx >> 3, c4 = (idx & 7) << 2;
            float4 v = *reinterpret_cast<const float4*>(B + (size_t)(n0 + r) * K + k0 + c4);
            Bs[r][c4 + 0] = f2tf32(v.x);
            Bs[r][c4 + 1] = f2tf32(v.y);
            Bs[r][c4 + 2] = f2tf32(v.z);
            Bs[r][c4 + 3] = f2tf32(v.w);
        }
        __syncthreads();

#pragma unroll
        for (int kk = 0; kk < GBK; kk += 8) {
            uint32_t af[2][4];
#pragma unroll
            for (int mm = 0; mm < 2; mm++) {
                int row = wm * 32 + mm * 16 + g;
                af[mm][0] = As[row][kk + tig];
                af[mm][1] = As[row + 8][kk + tig];
                af[mm][2] = As[row][kk + tig + 4];
                af[mm][3] = As[row + 8][kk + tig + 4];
            }
            uint32_t bf[4][2];
#pragma unroll
            for (int nn = 0; nn < 4; nn++) {
                int col = wn * 32 + nn * 8 + g;
                bf[nn][0] = Bs[col][kk + tig];
                bf[nn][1] = Bs[col][kk + tig + 4];
            }
#pragma unroll
            for (int mm = 0; mm < 2; mm++)
#pragma unroll
                for (int nn = 0; nn < 4; nn++)
                    mma_tf32(acc[mm][nn], af[mm], bf[nn]);
        }
        __syncthreads();
    }

#pragma unroll
    for (int mm = 0; mm < 2; mm++) {
        int r0 = m0 + wm * 32 + mm * 16 + g;
#pragma unroll
        for (int nn = 0; nn < 4; nn++) {
            int col = n0 + wn * 32 + nn * 8 + tig * 2;
            float b0 = bias[col], b1 = bias[col + 1];
            if (r0 < M) {
                float v0 = acc[mm][nn][0] + b0;
                float v1 = acc[mm][nn][1] + b1;
                C[(size_t)r0 * N + col]     = v0 > 0.f ? v0 : 0.f;
                C[(size_t)r0 * N + col + 1] = v1 > 0.f ? v1 : 0.f;
            }
            if (r0 + 8 < M) {
                float v2 = acc[mm][nn][2] + b0;
                float v3 = acc[mm][nn][3] + b1;
                C[(size_t)(r0 + 8) * N + col]     = v2 > 0.f ? v2 : 0.f;
                C[(size_t)(r0 + 8) * N + col + 1] = v3 > 0.f ? v3 : 0.f;
            }
        }
    }
}

// ---------------- transpose Wa1 (64x128) -> WaT (128x64) ----------------
__global__ void transpose_wa1_kernel(const float* __restrict__ Wa1, float* __restrict__ WaT) {
    int idx = blockIdx.x * blockDim.x + threadIdx.x;
    if (idx >= OUT_D * ATT_H) return;
    int k = idx / ATT_H;
    int j = idx % ATT_H;
    WaT[idx] = Wa1[j * OUT_D + k];
}

// ---------------- attention: warp per node ----------------
__global__ __launch_bounds__(256) void attention_kernel(
    const float* __restrict__ out, const float* __restrict__ WaT,
    const float* __restrict__ ba1, const float* __restrict__ Wa2,
    const float* __restrict__ ba2, float* __restrict__ att, int N)
{
    int warp = (blockIdx.x * blockDim.x + threadIdx.x) >> 5;
    int lane = threadIdx.x & 31;
    if (warp >= N) return;
    const float* o = out + (size_t)warp * OUT_D;
    float acc0 = ba1[lane];
    float acc1 = ba1[lane + 32];
#pragma unroll 4
    for (int k = 0; k < OUT_D; k++) {
        float ov = __ldg(o + k);
        acc0 = fmaf(WaT[k * ATT_H + lane],      ov, acc0);
        acc1 = fmaf(WaT[k * ATT_H + lane + 32], ov, acc1);
    }
    acc0 = fmaxf(acc0, 0.0f) * Wa2[lane];
    acc1 = fmaxf(acc1, 0.0f) * Wa2[lane + 32];
    float s = acc0 + acc1;
#pragma unroll
    for (int off = 16; off; off >>= 1) s += __shfl_xor_sync(0xffffffffu, s, off);
    if (lane == 0) att[warp] = 1.0f / (1.0f + expf(-(s + ba2[0])));
}

// ---------------- launch ----------------
extern "C" void kernel_launch(void* const* d_in, const int* in_sizes, int n_in,
                              void* d_out, int out_size)
{
    const float* x    = (const float*)d_in[0];
    const int*   ei   = (const int*)d_in[1];     // (2, E) int32: [src | tgt]
    const float* W1   = (const float*)d_in[2];
    const float* b1   = (const float*)d_in[3];
    const float* W2   = (const float*)d_in[4];
    const float* b2   = (const float*)d_in[5];
    const float* Wa1  = (const float*)d_in[6];
    const float* ba1  = (const float*)d_in[7];
    const float* Wa2  = (const float*)d_in[8];
    const float* ba2  = (const float*)d_in[9];

    const int E = in_sizes[1] / 2;
    const int* src = ei;
    const int* tgt = ei + E;

    float* out_ptr = (float*)d_out;                        // (N, 128)
    float* att_ptr = out_ptr + (size_t)NNODES * OUT_D;     // (N, 1)

    float* h_p;    cudaGetSymbolAddress((void**)&h_p,    g_h);
    float* h2_p;   cudaGetSymbolAddress((void**)&h2_p,   g_h2);
    float* inv_p;  cudaGetSymbolAddress((void**)&inv_p,  g_inv);
    int*   cnt_p;  cudaGetSymbolAddress((void**)&cnt_p,  g_cnt);
    int*   off_p;  cudaGetSymbolAddress((void**)&off_p,  g_off);
    int*   cur_p;  cudaGetSymbolAddress((void**)&cur_p,  g_cur);
    int*   bsum_p; cudaGetSymbolAddress((void**)&bsum_p, g_bsum);
    int*   bofs_p; cudaGetSymbolAddress((void**)&bofs_p, g_bofs);
    int*   srcs_p; cudaGetSymbolAddress((void**)&srcs_p, g_srcs);
    float* wat_p;  cudaGetSymbolAddress((void**)&wat_p,  g_WaT);

    // --- fork a side stream for the CSR build + Wa1 transpose (independent of GEMM1) ---
    cudaStream_t side;
    cudaStreamCreateWithFlags(&side, cudaStreamNonBlocking);
    cudaEvent_t ev_fork, ev_csr;
    cudaEventCreateWithFlags(&ev_fork, cudaEventDisableTiming);
    cudaEventCreateWithFlags(&ev_csr,  cudaEventDisableTiming);

    cudaEventRecord(ev_fork, 0);
    cudaStreamWaitEvent(side, ev_fork, 0);

    // side branch: transpose + CSR build (cnt was zeroed by the previous launch's scan3,
    // and is statically zero-initialized on the very first launch)
    transpose_wa1_kernel<<<(OUT_D * ATT_H + 255) / 256, 256, 0, side>>>(Wa1, wat_p);
    count_kernel<<<(E / 4 + 255) / 256, 256, 0, side>>>(tgt, cnt_p, E);
    scan1_kernel<<<SCAN_BLOCKS, SCAN_TPB, 0, side>>>(cnt_p, bsum_p);
    scan2_kernel<<<1, 64, 0, side>>>(bsum_p, bofs_p, off_p);
    scan3_kernel<<<SCAN_BLOCKS, SCAN_TPB, 0, side>>>(cnt_p, bofs_p, off_p, cur_p, inv_p);
    fill_kernel<<<(E / 4 + 255) / 256, 256, 0, side>>>(src, tgt, cur_p, srcs_p, E);
    cudaEventRecord(ev_csr, side);

    // main branch: h = relu(x @ W1^T + b1)  (tf32 tensor cores)
    {
        dim3 grid(HID / GBN, (NNODES + GBM - 1) / GBM);
        gemm_tf32_relu_kernel<<<grid, 256>>>(x, W1, b1, h_p, NNODES, HID, F_IN);
    }

    // join: gathers need both GEMM1 (h) and the CSR
    cudaStreamWaitEvent(0, ev_csr, 0);

    // --- two propagation rounds (ping-pong h <-> h2) ---
    {
        int gblocks = (NNODES + 3) / 4;
        gather_combine_kernel<<<gblocks, 256>>>(h_p,  h2_p, off_p, srcs_p, inv_p);
        gather_combine_kernel<<<gblocks, 256>>>(h2_p, h_p,  off_p, srcs_p, inv_p);
    }

    // --- out = relu(h @ W2^T + b2) -> directly into d_out (tf32) ---
    {
        dim3 grid(OUT_D / GBN, (NNODES + GBM - 1) / GBM);
        gemm_tf32_relu_kernel<<<grid, 256>>>(h_p, W2, b2, out_ptr, NNODES, OUT_D, HID);
    }

    // --- attention head (WaT already built on side branch, joined above) ---
    attention_kernel<<<(NNODES * 32 + 255) / 256, 256>>>(out_ptr, wat_p, ba1, Wa2, ba2,
                                                         att_ptr, NNODES);

    cudaEventDestroy(ev_fork);
    cudaEventDestroy(ev_csr);
    cudaStreamDestroy(side);
}

// round 9
// speedup vs baseline: 2.6030x; 1.0050x over previous
#include <cuda_runtime.h>
#include <cuda_bf16.h>
#include <math.h>
#include <stdint.h>

// ---------------- problem constants ----------------
#define NNODES   10000
#define F_IN     384
#define HID      256
#define OUT_D    128
#define ATT_H    64
#define EDGES_MAX 320000

#define SCAN_BLOCKS 40
#define SCAN_TPB    256   // 40*256 = 10240 >= NNODES

// ---------------- scratch (device globals; no allocation allowed) ----------------
__device__ float           g_h  [NNODES * HID];
__device__ float           g_h2 [NNODES * HID];
__device__ __nv_bfloat16   g_hb [NNODES * HID];   // bf16 shadow of h (neighbor reads)
__device__ __nv_bfloat16   g_hb2[NNODES * HID];   // bf16 shadow of h2
__device__ float g_inv[NNODES];
__device__ int   g_cnt[NNODES];          // zero-init; re-zeroed by scan3 each launch
__device__ int   g_off[NNODES + 1];
__device__ int   g_cur[NNODES];
__device__ int   g_bsum[SCAN_BLOCKS];
__device__ int   g_bofs[SCAN_BLOCKS];
__device__ int   g_srcs[EDGES_MAX];
__device__ float g_WaT[OUT_D * ATT_H];   // Wa1 transposed

// ---------------- count in-degree, 4 edges/thread ----------------
__global__ void count_kernel(const int* __restrict__ tgt, int* __restrict__ cnt, int E) {
    int i = (blockIdx.x * blockDim.x + threadIdx.x) * 4;
    if (i + 4 <= E) {
        int t0 = tgt[i], t1 = tgt[i + 1], t2 = tgt[i + 2], t3 = tgt[i + 3];
        atomicAdd(&cnt[t0], 1);
        atomicAdd(&cnt[t1], 1);
        atomicAdd(&cnt[t2], 1);
        atomicAdd(&cnt[t3], 1);
    } else {
        for (; i < E; i++) atomicAdd(&cnt[tgt[i]], 1);
    }
}

// ---------------- scan phase 1 ----------------
__global__ __launch_bounds__(SCAN_TPB) void scan1_kernel(
    const int* __restrict__ cnt, int* __restrict__ bsum)
{
    __shared__ int wsum[SCAN_TPB / 32];
    int idx = blockIdx.x * SCAN_TPB + threadIdx.x;
    int v = (idx < NNODES) ? cnt[idx] : 0;
    int lane = threadIdx.x & 31;
    int warp = threadIdx.x >> 5;
#pragma unroll
    for (int d = 16; d; d >>= 1) v += __shfl_xor_sync(0xffffffffu, v, d);
    if (lane == 0) wsum[warp] = v;
    __syncthreads();
    if (threadIdx.x == 0) {
        int s = 0;
#pragma unroll
        for (int w = 0; w < SCAN_TPB / 32; w++) s += wsum[w];
        bsum[blockIdx.x] = s;
    }
}

// ---------------- scan phase 2 ----------------
__global__ void scan2_kernel(const int* __restrict__ bsum, int* __restrict__ bofs,
                             int* __restrict__ off)
{
    int lane = threadIdx.x;
    int v = (lane < SCAN_BLOCKS) ? bsum[lane] : 0;
    int lane32 = lane & 31;
    int half = lane >> 5;
    int s = v;
#pragma unroll
    for (int d = 1; d < 32; d <<= 1) {
        int t = __shfl_up_sync(0xffffffffu, s, d);
        if (lane32 >= d) s += t;
    }
    __shared__ int w0tot;
    if (lane == 31) w0tot = s;
    __syncthreads();
    int incl = s + (half ? w0tot : 0);
    if (lane < SCAN_BLOCKS) bofs[lane] = incl - v;
    if (lane == SCAN_BLOCKS - 1) off[NNODES] = incl;
}

// ---------------- scan phase 3 ----------------
__global__ __launch_bounds__(SCAN_TPB) void scan3_kernel(
    int* __restrict__ cnt, const int* __restrict__ bofs,
    int* __restrict__ off, int* __restrict__ cur, float* __restrict__ inv)
{
    __shared__ int wsum[SCAN_TPB / 32];
    int idx = blockIdx.x * SCAN_TPB + threadIdx.x;
    int lane = threadIdx.x & 31;
    int warp = threadIdx.x >> 5;
    int v = (idx < NNODES) ? cnt[idx] : 0;

    int s = v;
#pragma unroll
    for (int d = 1; d < 32; d <<= 1) {
        int t = __shfl_up_sync(0xffffffffu, s, d);
        if (lane >= d) s += t;
    }
    if (lane == 31) wsum[warp] = s;
    __syncthreads();
    if (warp == 0) {
        int ws = (lane < SCAN_TPB / 32) ? wsum[lane] : 0;
#pragma unroll
        for (int d = 1; d < SCAN_TPB / 32; d <<= 1) {
            int t = __shfl_up_sync(0xffffffffu, ws, d);
            if (lane >= d) ws += t;
        }
        if (lane < SCAN_TPB / 32) wsum[lane] = ws;
    }
    __syncthreads();
    int excl = s - v + (warp ? wsum[warp - 1] : 0) + bofs[blockIdx.x];
    if (idx < NNODES) {
        off[idx] = excl;
        cur[idx] = excl;
        inv[idx] = 1.0f / ((float)v + 1.0f);
        cnt[idx] = 0;
    }
}

// ---------------- fill CSR buckets ----------------
__global__ void fill_kernel(const int* __restrict__ src, const int* __restrict__ tgt,
                            int* __restrict__ cur, int* __restrict__ srcs, int E)
{
    int i = (blockIdx.x * blockDim.x + threadIdx.x) * 4;
    if (i + 4 <= E) {
        int t0 = tgt[i], t1 = tgt[i + 1], t2 = tgt[i + 2], t3 = tgt[i + 3];
        int s0 = src[i], s1 = src[i + 1], s2 = src[i + 2], s3 = src[i + 3];
        int p0 = atomicAdd(&cur[t0], 1);
        int p1 = atomicAdd(&cur[t1], 1);
        int p2 = atomicAdd(&cur[t2], 1);
        int p3 = atomicAdd(&cur[t3], 1);
        srcs[p0] = s0;
        srcs[p1] = s1;
        srcs[p2] = s2;
        srcs[p3] = s3;
    } else {
        for (; i < E; i++) {
            int p = atomicAdd(&cur[tgt[i]], 1);
            srcs[p] = src[i];
        }
    }
}

// ---------------- fused gather(bf16 neighbors) + combine(fp32 self) ----------------
// hout[t] = 0.7*hin[t] + 0.3*inv[t]*sum_{s} bf16(hin[s]); also emits bf16 shadow of hout.
__device__ __forceinline__ void acc_bf16x4(float4& acc, uint2 p) {
    __nv_bfloat162 lo = *reinterpret_cast<__nv_bfloat162*>(&p.x);
    __nv_bfloat162 hi = *reinterpret_cast<__nv_bfloat162*>(&p.y);
    float2 f0 = __bfloat1622float2(lo);
    float2 f1 = __bfloat1622float2(hi);
    acc.x += f0.x; acc.y += f0.y; acc.z += f1.x; acc.w += f1.y;
}

__global__ __launch_bounds__(256) void gather_combine_kernel(
    const float* __restrict__ hin, const __nv_bfloat16* __restrict__ hbin,
    float* __restrict__ hout, __nv_bfloat16* __restrict__ hbout,
    const int* __restrict__ off, const int* __restrict__ srcs,
    const float* __restrict__ inv)
{
    int node = blockIdx.x * 4 + (threadIdx.x >> 6);
    if (node >= NNODES) return;
    int c = (threadIdx.x & 63) << 2;

    int beg = off[node];
    int end = off[node + 1];

    float4 acc = make_float4(0.f, 0.f, 0.f, 0.f);
    int i = beg;
    for (; i + 4 <= end; i += 4) {
        int s0 = __ldg(srcs + i);
        int s1 = __ldg(srcs + i + 1);
        int s2 = __ldg(srcs + i + 2);
        int s3 = __ldg(srcs + i + 3);
        uint2 p0 = *reinterpret_cast<const uint2*>(hbin + (size_t)s0 * HID + c);
        uint2 p1 = *reinterpret_cast<const uint2*>(hbin + (size_t)s1 * HID + c);
        uint2 p2 = *reinterpret_cast<const uint2*>(hbin + (size_t)s2 * HID + c);
        uint2 p3 = *reinterpret_cast<const uint2*>(hbin + (size_t)s3 * HID + c);
        acc_bf16x4(acc, p0);
        acc_bf16x4(acc, p1);
        acc_bf16x4(acc, p2);
        acc_bf16x4(acc, p3);
    }
    for (; i < end; i++) {
        int s0 = __ldg(srcs + i);
        uint2 p0 = *reinterpret_cast<const uint2*>(hbin + (size_t)s0 * HID + c);
        acc_bf16x4(acc, p0);
    }

    float sc = 0.3f * inv[node];
    float4 hv = *reinterpret_cast<const float4*>(hin + (size_t)node * HID + c);
    hv.x = 0.7f * hv.x + sc * acc.x;
    hv.y = 0.7f * hv.y + sc * acc.y;
    hv.z = 0.7f * hv.z + sc * acc.z;
    hv.w = 0.7f * hv.w + sc * acc.w;
    *reinterpret_cast<float4*>(hout + (size_t)node * HID + c) = hv;

    uint2 pk;
    __nv_bfloat162 lo = __floats2bfloat162_rn(hv.x, hv.y);
    __nv_bfloat162 hi = __floats2bfloat162_rn(hv.z, hv.w);
    pk.x = *reinterpret_cast<uint32_t*>(&lo);
    pk.y = *reinterpret_cast<uint32_t*>(&hi);
    *reinterpret_cast<uint2*>(hbout + (size_t)node * HID + c) = pk;
}

// ---------------- tf32 tensor-core GEMM (double-buffered): C = relu(A@B^T + bias) ----------------
// Optionally emits a bf16 shadow (Cb != nullptr).
#define GBM 128
#define GBN 64
#define GBK 32
#define SKA 36

__device__ __forceinline__ uint32_t f2tf32(float x) {
    uint32_t r;
    asm("cvt.rna.tf32.f32 %0, %1;" : "=r"(r) : "f"(x));
    return r;
}

__device__ __forceinline__ void mma_tf32(float* c, const uint32_t* a, const uint32_t* b) {
    asm volatile(
        "mma.sync.aligned.m16n8k8.row.col.f32.tf32.tf32.f32 "
        "{%0,%1,%2,%3}, {%4,%5,%6,%7}, {%8,%9}, {%0,%1,%2,%3};"
        : "+f"(c[0]), "+f"(c[1]), "+f"(c[2]), "+f"(c[3])
        : "r"(a[0]), "r"(a[1]), "r"(a[2]), "r"(a[3]), "r"(b[0]), "r"(b[1]));
}

__global__ __launch_bounds__(256) void gemm_tf32_relu_kernel(
    const float* __restrict__ A, const float* __restrict__ B,
    const float* __restrict__ bias, float* __restrict__ C,
    __nv_bfloat16* __restrict__ Cb,
    int M, int N, int K)
{
    __shared__ uint32_t As[GBM][SKA];
    __shared__ uint32_t Bs[GBN][SKA];

    const int tid  = threadIdx.x;
    const int lane = tid & 31;
    const int warp = tid >> 5;
    const int wm = warp >> 1;
    const int wn = warp & 1;
    const int g   = lane >> 2;
    const int tig = lane & 3;
    const int m0 = blockIdx.y * GBM;
    const int n0 = blockIdx.x * GBN;

    const int ar = tid >> 3;            // A-tile row this thread loads (0..127 via +off)
    const int ac4 = (tid & 7) << 2;     // k-offset within tile

    float acc[2][4][4];
#pragma unroll
    for (int mm = 0; mm < 2; mm++)
#pragma unroll
        for (int nn = 0; nn < 4; nn++)
#pragma unroll
            for (int q = 0; q < 4; q++) acc[mm][nn][q] = 0.0f;

    float4 ra[4], rb[2];
    // preload k0 = 0
#pragma unroll
    for (int it = 0; it < 4; it++) {
        int r = ar + it * 32;
        int gm = m0 + r;
        ra[it] = (gm < M) ? *reinterpret_cast<const float4*>(A + (size_t)gm * K + ac4)
                          : make_float4(0.f, 0.f, 0.f, 0.f);
    }
#pragma unroll
    for (int it = 0; it < 2; it++) {
        int r = ar + it * 32;
        rb[it] = *reinterpret_cast<const float4*>(B + (size_t)(n0 + r) * K + ac4);
    }

    for (int k0 = 0; k0 < K; k0 += GBK) {
        // store current regs -> smem
#pragma unroll
        for (int it = 0; it < 4; it++) {
            int r = ar + it * 32;
            As[r][ac4 + 0] = f2tf32(ra[it].x);
            As[r][ac4 + 1] = f2tf32(ra[it].y);
            As[r][ac4 + 2] = f2tf32(ra[it].z);
            As[r][ac4 + 3] = f2tf32(ra[it].w);
        }
#pragma unroll
        for (int it = 0; it < 2; it++) {
            int r = ar + it * 32;
            Bs[r][ac4 + 0] = f2tf32(rb[it].x);
            Bs[r][ac4 + 1] = f2tf32(rb[it].y);
            Bs[r][ac4 + 2] = f2tf32(rb[it].z);
            Bs[r][ac4 + 3] = f2tf32(rb[it].w);
        }
        __syncthreads();

        // prefetch next tile while computing this one
        int kn = k0 + GBK;
        if (kn < K) {
#pragma unroll
            for (int it = 0; it < 4; it++) {
                int r = ar + it * 32;
                int gm = m0 + r;
                ra[it] = (gm < M) ? *reinterpret_cast<const float4*>(A + (size_t)gm * K + kn + ac4)
                                  : make_float4(0.f, 0.f, 0.f, 0.f);
            }
#pragma unroll
            for (int it = 0; it < 2; it++) {
                int r = ar + it * 32;
                rb[it] = *reinterpret_cast<const float4*>(B + (size_t)(n0 + r) * K + kn + ac4);
            }
        }

#pragma unroll
        for (int kk = 0; kk < GBK; kk += 8) {
            uint32_t af[2][4];
#pragma unroll
            for (int mm = 0; mm < 2; mm++) {
                int row = wm * 32 + mm * 16 + g;
                af[mm][0] = As[row][kk + tig];
                af[mm][1] = As[row + 8][kk + tig];
                af[mm][2] = As[row][kk + tig + 4];
                af[mm][3] = As[row + 8][kk + tig + 4];
            }
            uint32_t bf[4][2];
#pragma unroll
            for (int nn = 0; nn < 4; nn++) {
                int col = wn * 32 + nn * 8 + g;
                bf[nn][0] = Bs[col][kk + tig];
                bf[nn][1] = Bs[col][kk + tig + 4];
            }
#pragma unroll
            for (int mm = 0; mm < 2; mm++)
#pragma unroll
                for (int nn = 0; nn < 4; nn++)
                    mma_tf32(acc[mm][nn], af[mm], bf[nn]);
        }
        __syncthreads();
    }

    // epilogue: bias + relu (+ optional bf16 shadow)
#pragma unroll
    for (int mm = 0; mm < 2; mm++) {
        int r0 = m0 + wm * 32 + mm * 16 + g;
#pragma unroll
        for (int nn = 0; nn < 4; nn++) {
            int col = n0 + wn * 32 + nn * 8 + tig * 2;
            float b0 = bias[col], b1 = bias[col + 1];
            if (r0 < M) {
                float v0 = fmaxf(acc[mm][nn][0] + b0, 0.f);
                float v1 = fmaxf(acc[mm][nn][1] + b1, 0.f);
                C[(size_t)r0 * N + col]     = v0;
                C[(size_t)r0 * N + col + 1] = v1;
                if (Cb) {
                    __nv_bfloat162 p = __floats2bfloat162_rn(v0, v1);
                    *reinterpret_cast<uint32_t*>(Cb + (size_t)r0 * N + col) =
                        *reinterpret_cast<uint32_t*>(&p);
                }
            }
            if (r0 + 8 < M) {
                float v2 = fmaxf(acc[mm][nn][2] + b0, 0.f);
                float v3 = fmaxf(acc[mm][nn][3] + b1, 0.f);
                C[(size_t)(r0 + 8) * N + col]     = v2;
                C[(size_t)(r0 + 8) * N + col + 1] = v3;
                if (Cb) {
                    __nv_bfloat162 p = __floats2bfloat162_rn(v2, v3);
                    *reinterpret_cast<uint32_t*>(Cb + (size_t)(r0 + 8) * N + col) =
                        *reinterpret_cast<uint32_t*>(&p);
                }
            }
        }
    }
}

// ---------------- transpose Wa1 (64x128) -> WaT (128x64) ----------------
__global__ void transpose_wa1_kernel(const float* __restrict__ Wa1, float* __restrict__ WaT) {
    int idx = blockIdx.x * blockDim.x + threadIdx.x;
    if (idx >= OUT_D * ATT_H) return;
    int k = idx / ATT_H;
    int j = idx % ATT_H;
    WaT[idx] = Wa1[j * OUT_D + k];
}

// ---------------- attention: warp per node ----------------
__global__ __launch_bounds__(256) void attention_kernel(
    const float* __restrict__ out, const float* __restrict__ WaT,
    const float* __restrict__ ba1, const float* __restrict__ Wa2,
    const float* __restrict__ ba2, float* __restrict__ att, int N)
{
    int warp = (blockIdx.x * blockDim.x + threadIdx.x) >> 5;
    int lane = threadIdx.x & 31;
    if (warp >= N) return;
    const float* o = out + (size_t)warp * OUT_D;
    float acc0 = ba1[lane];
    float acc1 = ba1[lane + 32];
#pragma unroll 4
    for (int k = 0; k < OUT_D; k++) {
        float ov = __ldg(o + k);
        acc0 = fmaf(WaT[k * ATT_H + lane],      ov, acc0);
        acc1 = fmaf(WaT[k * ATT_H + lane + 32], ov, acc1);
    }
    acc0 = fmaxf(acc0, 0.0f) * Wa2[lane];
    acc1 = fmaxf(acc1, 0.0f) * Wa2[lane + 32];
    float s = acc0 + acc1;
#pragma unroll
    for (int off = 16; off; off >>= 1) s += __shfl_xor_sync(0xffffffffu, s, off);
    if (lane == 0) att[warp] = 1.0f / (1.0f + expf(-(s + ba2[0])));
}

// ---------------- launch ----------------
extern "C" void kernel_launch(void* const* d_in, const int* in_sizes, int n_in,
                              void* d_out, int out_size)
{
    const float* x    = (const float*)d_in[0];
    const int*   ei   = (const int*)d_in[1];     // (2, E) int32: [src | tgt]
    const float* W1   = (const float*)d_in[2];
    const float* b1   = (const float*)d_in[3];
    const float* W2   = (const float*)d_in[4];
    const float* b2   = (const float*)d_in[5];
    const float* Wa1  = (const float*)d_in[6];
    const float* ba1  = (const float*)d_in[7];
    const float* Wa2  = (const float*)d_in[8];
    const float* ba2  = (const float*)d_in[9];

    const int E = in_sizes[1] / 2;
    const int* src = ei;
    const int* tgt = ei + E;

    float* out_ptr = (float*)d_out;                        // (N, 128)
    float* att_ptr = out_ptr + (size_t)NNODES * OUT_D;     // (N, 1)

    float*         h_p;    cudaGetSymbolAddress((void**)&h_p,    g_h);
    float*         h2_p;   cudaGetSymbolAddress((void**)&h2_p,   g_h2);
    __nv_bfloat16* hb_p;   cudaGetSymbolAddress((void**)&hb_p,   g_hb);
    __nv_bfloat16* hb2_p;  cudaGetSymbolAddress((void**)&hb2_p,  g_hb2);
    float*         inv_p;  cudaGetSymbolAddress((void**)&inv_p,  g_inv);
    int*           cnt_p;  cudaGetSymbolAddress((void**)&cnt_p,  g_cnt);
    int*           off_p;  cudaGetSymbolAddress((void**)&off_p,  g_off);
    int*           cur_p;  cudaGetSymbolAddress((void**)&cur_p,  g_cur);
    int*           bsum_p; cudaGetSymbolAddress((void**)&bsum_p, g_bsum);
    int*           bofs_p; cudaGetSymbolAddress((void**)&bofs_p, g_bofs);
    int*           srcs_p; cudaGetSymbolAddress((void**)&srcs_p, g_srcs);
    float*         wat_p;  cudaGetSymbolAddress((void**)&wat_p,  g_WaT);

    // --- fork a side stream for CSR build + Wa1 transpose (independent of GEMM1) ---
    cudaStream_t side;
    cudaStreamCreateWithFlags(&side, cudaStreamNonBlocking);
    cudaEvent_t ev_fork, ev_csr;
    cudaEventCreateWithFlags(&ev_fork, cudaEventDisableTiming);
    cudaEventCreateWithFlags(&ev_csr,  cudaEventDisableTiming);

    cudaEventRecord(ev_fork, 0);
    cudaStreamWaitEvent(side, ev_fork, 0);

    transpose_wa1_kernel<<<(OUT_D * ATT_H + 255) / 256, 256, 0, side>>>(Wa1, wat_p);
    count_kernel<<<(E / 4 + 255) / 256, 256, 0, side>>>(tgt, cnt_p, E);
    scan1_kernel<<<SCAN_BLOCKS, SCAN_TPB, 0, side>>>(cnt_p, bsum_p);
    scan2_kernel<<<1, 64, 0, side>>>(bsum_p, bofs_p, off_p);
    scan3_kernel<<<SCAN_BLOCKS, SCAN_TPB, 0, side>>>(cnt_p, bofs_p, off_p, cur_p, inv_p);
    fill_kernel<<<(E / 4 + 255) / 256, 256, 0, side>>>(src, tgt, cur_p, srcs_p, E);
    cudaEventRecord(ev_csr, side);

    // main: h = relu(x @ W1^T + b1), fp32 + bf16 shadow
    {
        dim3 grid(HID / GBN, (NNODES + GBM - 1) / GBM);
        gemm_tf32_relu_kernel<<<grid, 256>>>(x, W1, b1, h_p, hb_p, NNODES, HID, F_IN);
    }

    cudaStreamWaitEvent(0, ev_csr, 0);

    // two propagation rounds (ping-pong)
    {
        int gblocks = (NNODES + 3) / 4;
        gather_combine_kernel<<<gblocks, 256>>>(h_p,  hb_p,  h2_p, hb2_p, off_p, srcs_p, inv_p);
        gather_combine_kernel<<<gblocks, 256>>>(h2_p, hb2_p, h_p,  hb_p,  off_p, srcs_p, inv_p);
    }

    // out = relu(h @ W2^T + b2) -> d_out (no shadow)
    {
        dim3 grid(OUT_D / GBN, (NNODES + GBM - 1) / GBM);
        gemm_tf32_relu_kernel<<<grid, 256>>>(h_p, W2, b2, out_ptr, (__nv_bfloat16*)nullptr,
                                             NNODES, OUT_D, HID);
    }

    attention_kernel<<<(NNODES * 32 + 255) / 256, 256>>>(out_ptr, wat_p, ba1, Wa2, ba2,
                                                         att_ptr, NNODES);

    cudaEventDestroy(ev_fork);
    cudaEventDestroy(ev_csr);
    cudaStreamDestroy(side);
}

// round 10
// speedup vs baseline: 3.0350x; 1.1660x over previous
#include <cuda_runtime.h>
#include <cuda_bf16.h>
#include <math.h>
#include <stdint.h>

// ---------------- problem constants ----------------
#define NNODES   10000
#define F_IN     384
#define HID      256
#define OUT_D    128
#define ATT_H    64
#define EDGES_MAX 320000

#define SCAN_BLOCKS 40
#define SCAN_TPB    256   // 40*256 = 10240 >= NNODES

// ---------------- scratch (device globals; no allocation allowed) ----------------
__device__ float           g_h  [NNODES * HID];     // relu(x W1^T + b1), 256-wide
__device__ float           g_z  [NNODES * OUT_D];   // h @ W2^T (pre-bias/relu), 128-wide
__device__ float           g_z2 [NNODES * OUT_D];
__device__ __nv_bfloat16   g_zb [NNODES * OUT_D];   // bf16 shadows for neighbor reads
__device__ __nv_bfloat16   g_zb2[NNODES * OUT_D];
__device__ float g_inv[NNODES];
__device__ int   g_cnt[NNODES];          // zero-init; re-zeroed by scan3 each launch
__device__ int   g_off[NNODES + 1];
__device__ int   g_cur[NNODES];
__device__ int   g_bsum[SCAN_BLOCKS];
__device__ int   g_bofs[SCAN_BLOCKS];
__device__ int   g_srcs[EDGES_MAX];
__device__ float g_WaT[OUT_D * ATT_H];   // Wa1 transposed

// ---------------- count in-degree, 4 edges/thread ----------------
__global__ void count_kernel(const int* __restrict__ tgt, int* __restrict__ cnt, int E) {
    int i = (blockIdx.x * blockDim.x + threadIdx.x) * 4;
    if (i + 4 <= E) {
        int t0 = tgt[i], t1 = tgt[i + 1], t2 = tgt[i + 2], t3 = tgt[i + 3];
        atomicAdd(&cnt[t0], 1);
        atomicAdd(&cnt[t1], 1);
        atomicAdd(&cnt[t2], 1);
        atomicAdd(&cnt[t3], 1);
    } else {
        for (; i < E; i++) atomicAdd(&cnt[tgt[i]], 1);
    }
}

// ---------------- scan phase 1 ----------------
__global__ __launch_bounds__(SCAN_TPB) void scan1_kernel(
    const int* __restrict__ cnt, int* __restrict__ bsum)
{
    __shared__ int wsum[SCAN_TPB / 32];
    int idx = blockIdx.x * SCAN_TPB + threadIdx.x;
    int v = (idx < NNODES) ? cnt[idx] : 0;
    int lane = threadIdx.x & 31;
    int warp = threadIdx.x >> 5;
#pragma unroll
    for (int d = 16; d; d >>= 1) v += __shfl_xor_sync(0xffffffffu, v, d);
    if (lane == 0) wsum[warp] = v;
    __syncthreads();
    if (threadIdx.x == 0) {
        int s = 0;
#pragma unroll
        for (int w = 0; w < SCAN_TPB / 32; w++) s += wsum[w];
        bsum[blockIdx.x] = s;
    }
}

// ---------------- scan phase 2 ----------------
__global__ void scan2_kernel(const int* __restrict__ bsum, int* __restrict__ bofs,
                             int* __restrict__ off)
{
    int lane = threadIdx.x;
    int v = (lane < SCAN_BLOCKS) ? bsum[lane] : 0;
    int lane32 = lane & 31;
    int half = lane >> 5;
    int s = v;
#pragma unroll
    for (int d = 1; d < 32; d <<= 1) {
        int t = __shfl_up_sync(0xffffffffu, s, d);
        if (lane32 >= d) s += t;
    }
    __shared__ int w0tot;
    if (lane == 31) w0tot = s;
    __syncthreads();
    int incl = s + (half ? w0tot : 0);
    if (lane < SCAN_BLOCKS) bofs[lane] = incl - v;
    if (lane == SCAN_BLOCKS - 1) off[NNODES] = incl;
}

// ---------------- scan phase 3 ----------------
__global__ __launch_bounds__(SCAN_TPB) void scan3_kernel(
    int* __restrict__ cnt, const int* __restrict__ bofs,
    int* __restrict__ off, int* __restrict__ cur, float* __restrict__ inv)
{
    __shared__ int wsum[SCAN_TPB / 32];
    int idx = blockIdx.x * SCAN_TPB + threadIdx.x;
    int lane = threadIdx.x & 31;
    int warp = threadIdx.x >> 5;
    int v = (idx < NNODES) ? cnt[idx] : 0;

    int s = v;
#pragma unroll
    for (int d = 1; d < 32; d <<= 1) {
        int t = __shfl_up_sync(0xffffffffu, s, d);
        if (lane >= d) s += t;
    }
    if (lane == 31) wsum[warp] = s;
    __syncthreads();
    if (warp == 0) {
        int ws = (lane < SCAN_TPB / 32) ? wsum[lane] : 0;
#pragma unroll
        for (int d = 1; d < SCAN_TPB / 32; d <<= 1) {
            int t = __shfl_up_sync(0xffffffffu, ws, d);
            if (lane >= d) ws += t;
        }
        if (lane < SCAN_TPB / 32) wsum[lane] = ws;
    }
    __syncthreads();
    int excl = s - v + (warp ? wsum[warp - 1] : 0) + bofs[blockIdx.x];
    if (idx < NNODES) {
        off[idx] = excl;
        cur[idx] = excl;
        inv[idx] = 1.0f / ((float)v + 1.0f);
        cnt[idx] = 0;
    }
}

// ---------------- fill CSR buckets ----------------
__global__ void fill_kernel(const int* __restrict__ src, const int* __restrict__ tgt,
                            int* __restrict__ cur, int* __restrict__ srcs, int E)
{
    int i = (blockIdx.x * blockDim.x + threadIdx.x) * 4;
    if (i + 4 <= E) {
        int t0 = tgt[i], t1 = tgt[i + 1], t2 = tgt[i + 2], t3 = tgt[i + 3];
        int s0 = src[i], s1 = src[i + 1], s2 = src[i + 2], s3 = src[i + 3];
        int p0 = atomicAdd(&cur[t0], 1);
        int p1 = atomicAdd(&cur[t1], 1);
        int p2 = atomicAdd(&cur[t2], 1);
        int p3 = atomicAdd(&cur[t3], 1);
        srcs[p0] = s0;
        srcs[p1] = s1;
        srcs[p2] = s2;
        srcs[p3] = s3;
    } else {
        for (; i < E; i++) {
            int p = atomicAdd(&cur[tgt[i]], 1);
            srcs[p] = src[i];
        }
    }
}

// ---------------- 128-wide fused gather + combine (propagation in z-space) ----------------
// One warp per node; each lane owns 4 floats (32*4 = 128).
// zout[t] = 0.7*zin[t] + 0.3*inv[t]*sum_s bf16(zin[s])     [+ b2, relu if final]
__device__ __forceinline__ void acc_bf16x4(float4& acc, uint2 p) {
    __nv_bfloat162 lo = *reinterpret_cast<__nv_bfloat162*>(&p.x);
    __nv_bfloat162 hi = *reinterpret_cast<__nv_bfloat162*>(&p.y);
    float2 f0 = __bfloat1622float2(lo);
    float2 f1 = __bfloat1622float2(hi);
    acc.x += f0.x; acc.y += f0.y; acc.z += f1.x; acc.w += f1.y;
}

__global__ __launch_bounds__(256) void gather_combine128_kernel(
    const float* __restrict__ zin, const __nv_bfloat16* __restrict__ zbin,
    float* __restrict__ zout, __nv_bfloat16* __restrict__ zbout,
    const float* __restrict__ b2,        // non-null => final pass: +bias, relu, no shadow
    const int* __restrict__ off, const int* __restrict__ srcs,
    const float* __restrict__ inv)
{
    int node = blockIdx.x * 8 + (threadIdx.x >> 5);
    if (node >= NNODES) return;
    int c = (threadIdx.x & 31) << 2;

    int beg = off[node];
    int end = off[node + 1];

    float4 acc = make_float4(0.f, 0.f, 0.f, 0.f);
    int i = beg;
    for (; i + 4 <= end; i += 4) {
        int s0 = __ldg(srcs + i);
        int s1 = __ldg(srcs + i + 1);
        int s2 = __ldg(srcs + i + 2);
        int s3 = __ldg(srcs + i + 3);
        uint2 p0 = *reinterpret_cast<const uint2*>(zbin + (size_t)s0 * OUT_D + c);
        uint2 p1 = *reinterpret_cast<const uint2*>(zbin + (size_t)s1 * OUT_D + c);
        uint2 p2 = *reinterpret_cast<const uint2*>(zbin + (size_t)s2 * OUT_D + c);
        uint2 p3 = *reinterpret_cast<const uint2*>(zbin + (size_t)s3 * OUT_D + c);
        acc_bf16x4(acc, p0);
        acc_bf16x4(acc, p1);
        acc_bf16x4(acc, p2);
        acc_bf16x4(acc, p3);
    }
    for (; i < end; i++) {
        int s0 = __ldg(srcs + i);
        uint2 p0 = *reinterpret_cast<const uint2*>(zbin + (size_t)s0 * OUT_D + c);
        acc_bf16x4(acc, p0);
    }

    float sc = 0.3f * inv[node];
    float4 zv = *reinterpret_cast<const float4*>(zin + (size_t)node * OUT_D + c);
    zv.x = 0.7f * zv.x + sc * acc.x;
    zv.y = 0.7f * zv.y + sc * acc.y;
    zv.z = 0.7f * zv.z + sc * acc.z;
    zv.w = 0.7f * zv.w + sc * acc.w;

    if (b2) {
        float4 bv = *reinterpret_cast<const float4*>(b2 + c);
        zv.x = fmaxf(zv.x + bv.x, 0.f);
        zv.y = fmaxf(zv.y + bv.y, 0.f);
        zv.z = fmaxf(zv.z + bv.z, 0.f);
        zv.w = fmaxf(zv.w + bv.w, 0.f);
        *reinterpret_cast<float4*>(zout + (size_t)node * OUT_D + c) = zv;
    } else {
        *reinterpret_cast<float4*>(zout + (size_t)node * OUT_D + c) = zv;
        uint2 pk;
        __nv_bfloat162 lo = __floats2bfloat162_rn(zv.x, zv.y);
        __nv_bfloat162 hi = __floats2bfloat162_rn(zv.z, zv.w);
        pk.x = *reinterpret_cast<uint32_t*>(&lo);
        pk.y = *reinterpret_cast<uint32_t*>(&hi);
        *reinterpret_cast<uint2*>(zbout + (size_t)node * OUT_D + c) = pk;
    }
}

// ---------------- tf32 tensor-core GEMM (double-buffered) ----------------
// C = [relu]( A @ B^T [+ bias] ); optional bf16 shadow.
#define GBM 128
#define GBN 64
#define GBK 32
#define SKA 36

__device__ __forceinline__ uint32_t f2tf32(float x) {
    uint32_t r;
    asm("cvt.rna.tf32.f32 %0, %1;" : "=r"(r) : "f"(x));
    return r;
}

__device__ __forceinline__ void mma_tf32(float* c, const uint32_t* a, const uint32_t* b) {
    asm volatile(
        "mma.sync.aligned.m16n8k8.row.col.f32.tf32.tf32.f32 "
        "{%0,%1,%2,%3}, {%4,%5,%6,%7}, {%8,%9}, {%0,%1,%2,%3};"
        : "+f"(c[0]), "+f"(c[1]), "+f"(c[2]), "+f"(c[3])
        : "r"(a[0]), "r"(a[1]), "r"(a[2]), "r"(a[3]), "r"(b[0]), "r"(b[1]));
}

__global__ __launch_bounds__(256) void gemm_tf32_kernel(
    const float* __restrict__ A, const float* __restrict__ B,
    const float* __restrict__ bias,          // nullable
    float* __restrict__ C,
    __nv_bfloat16* __restrict__ Cb,          // nullable
    int M, int N, int K, int do_relu)
{
    __shared__ uint32_t As[GBM][SKA];
    __shared__ uint32_t Bs[GBN][SKA];

    const int tid  = threadIdx.x;
    const int lane = tid & 31;
    const int warp = tid >> 5;
    const int wm = warp >> 1;
    const int wn = warp & 1;
    const int g   = lane >> 2;
    const int tig = lane & 3;
    const int m0 = blockIdx.y * GBM;
    const int n0 = blockIdx.x * GBN;

    const int ar = tid >> 3;
    const int ac4 = (tid & 7) << 2;

    float acc[2][4][4];
#pragma unroll
    for (int mm = 0; mm < 2; mm++)
#pragma unroll
        for (int nn = 0; nn < 4; nn++)
#pragma unroll
            for (int q = 0; q < 4; q++) acc[mm][nn][q] = 0.0f;

    float4 ra[4], rb[2];
#pragma unroll
    for (int it = 0; it < 4; it++) {
        int r = ar + it * 32;
        int gm = m0 + r;
        ra[it] = (gm < M) ? *reinterpret_cast<const float4*>(A + (size_t)gm * K + ac4)
                          : make_float4(0.f, 0.f, 0.f, 0.f);
    }
#pragma unroll
    for (int it = 0; it < 2; it++) {
        int r = ar + it * 32;
        rb[it] = *reinterpret_cast<const float4*>(B + (size_t)(n0 + r) * K + ac4);
    }

    for (int k0 = 0; k0 < K; k0 += GBK) {
#pragma unroll
        for (int it = 0; it < 4; it++) {
            int r = ar + it * 32;
            As[r][ac4 + 0] = f2tf32(ra[it].x);
            As[r][ac4 + 1] = f2tf32(ra[it].y);
            As[r][ac4 + 2] = f2tf32(ra[it].z);
            As[r][ac4 + 3] = f2tf32(ra[it].w);
        }
#pragma unroll
        for (int it = 0; it < 2; it++) {
            int r = ar + it * 32;
            Bs[r][ac4 + 0] = f2tf32(rb[it].x);
            Bs[r][ac4 + 1] = f2tf32(rb[it].y);
            Bs[r][ac4 + 2] = f2tf32(rb[it].z);
            Bs[r][ac4 + 3] = f2tf32(rb[it].w);
        }
        __syncthreads();

        int kn = k0 + GBK;
        if (kn < K) {
#pragma unroll
            for (int it = 0; it < 4; it++) {
                int r = ar + it * 32;
                int gm = m0 + r;
                ra[it] = (gm < M) ? *reinterpret_cast<const float4*>(A + (size_t)gm * K + kn + ac4)
                                  : make_float4(0.f, 0.f, 0.f, 0.f);
            }
#pragma unroll
            for (int it = 0; it < 2; it++) {
                int r = ar + it * 32;
                rb[it] = *reinterpret_cast<const float4*>(B + (size_t)(n0 + r) * K + kn + ac4);
            }
        }

#pragma unroll
        for (int kk = 0; kk < GBK; kk += 8) {
            uint32_t af[2][4];
#pragma unroll
            for (int mm = 0; mm < 2; mm++) {
                int row = wm * 32 + mm * 16 + g;
                af[mm][0] = As[row][kk + tig];
                af[mm][1] = As[row + 8][kk + tig];
                af[mm][2] = As[row][kk + tig + 4];
                af[mm][3] = As[row + 8][kk + tig + 4];
            }
            uint32_t bf[4][2];
#pragma unroll
            for (int nn = 0; nn < 4; nn++) {
                int col = wn * 32 + nn * 8 + g;
                bf[nn][0] = Bs[col][kk + tig];
                bf[nn][1] = Bs[col][kk + tig + 4];
            }
#pragma unroll
            for (int mm = 0; mm < 2; mm++)
#pragma unroll
                for (int nn = 0; nn < 4; nn++)
                    mma_tf32(acc[mm][nn], af[mm], bf[nn]);
        }
        __syncthreads();
    }

#pragma unroll
    for (int mm = 0; mm < 2; mm++) {
        int r0 = m0 + wm * 32 + mm * 16 + g;
#pragma unroll
        for (int nn = 0; nn < 4; nn++) {
            int col = n0 + wn * 32 + nn * 8 + tig * 2;
            float b0 = bias ? bias[col]     : 0.f;
            float b1 = bias ? bias[col + 1] : 0.f;
#pragma unroll
            for (int half = 0; half < 2; half++) {
                int r = r0 + half * 8;
                if (r >= M) continue;
                float v0 = acc[mm][nn][half * 2 + 0] + b0;
                float v1 = acc[mm][nn][half * 2 + 1] + b1;
                if (do_relu) { v0 = fmaxf(v0, 0.f); v1 = fmaxf(v1, 0.f); }
                C[(size_t)r * N + col]     = v0;
                C[(size_t)r * N + col + 1] = v1;
                if (Cb) {
                    __nv_bfloat162 p = __floats2bfloat162_rn(v0, v1);
                    *reinterpret_cast<uint32_t*>(Cb + (size_t)r * N + col) =
                        *reinterpret_cast<uint32_t*>(&p);
                }
            }
        }
    }
}

// ---------------- transpose Wa1 (64x128) -> WaT (128x64) ----------------
__global__ void transpose_wa1_kernel(const float* __restrict__ Wa1, float* __restrict__ WaT) {
    int idx = blockIdx.x * blockDim.x + threadIdx.x;
    if (idx >= OUT_D * ATT_H) return;
    int k = idx / ATT_H;
    int j = idx % ATT_H;
    WaT[idx] = Wa1[j * OUT_D + k];
}

// ---------------- attention: warp per node ----------------
__global__ __launch_bounds__(256) void attention_kernel(
    const float* __restrict__ out, const float* __restrict__ WaT,
    const float* __restrict__ ba1, const float* __restrict__ Wa2,
    const float* __restrict__ ba2, float* __restrict__ att, int N)
{
    int warp = (blockIdx.x * blockDim.x + threadIdx.x) >> 5;
    int lane = threadIdx.x & 31;
    if (warp >= N) return;
    const float* o = out + (size_t)warp * OUT_D;
    float acc0 = ba1[lane];
    float acc1 = ba1[lane + 32];
#pragma unroll 4
    for (int k = 0; k < OUT_D; k++) {
        float ov = __ldg(o + k);
        acc0 = fmaf(WaT[k * ATT_H + lane],      ov, acc0);
        acc1 = fmaf(WaT[k * ATT_H + lane + 32], ov, acc1);
    }
    acc0 = fmaxf(acc0, 0.0f) * Wa2[lane];
    acc1 = fmaxf(acc1, 0.0f) * Wa2[lane + 32];
    float s = acc0 + acc1;
#pragma unroll
    for (int off = 16; off; off >>= 1) s += __shfl_xor_sync(0xffffffffu, s, off);
    if (lane == 0) att[warp] = 1.0f / (1.0f + expf(-(s + ba2[0])));
}

// ---------------- launch ----------------
extern "C" void kernel_launch(void* const* d_in, const int* in_sizes, int n_in,
                              void* d_out, int out_size)
{
    const float* x    = (const float*)d_in[0];
    const int*   ei   = (const int*)d_in[1];     // (2, E) int32: [src | tgt]
    const float* W1   = (const float*)d_in[2];
    const float* b1   = (const float*)d_in[3];
    const float* W2   = (const float*)d_in[4];
    const float* b2   = (const float*)d_in[5];
    const float* Wa1  = (const float*)d_in[6];
    const float* ba1  = (const float*)d_in[7];
    const float* Wa2  = (const float*)d_in[8];
    const float* ba2  = (const float*)d_in[9];

    const int E = in_sizes[1] / 2;
    const int* src = ei;
    const int* tgt = ei + E;

    float* out_ptr = (float*)d_out;                        // (N, 128)
    float* att_ptr = out_ptr + (size_t)NNODES * OUT_D;     // (N, 1)

    float*         h_p;    cudaGetSymbolAddress((void**)&h_p,    g_h);
    float*         z_p;    cudaGetSymbolAddress((void**)&z_p,    g_z);
    float*         z2_p;   cudaGetSymbolAddress((void**)&z2_p,   g_z2);
    __nv_bfloat16* zb_p;   cudaGetSymbolAddress((void**)&zb_p,   g_zb);
    __nv_bfloat16* zb2_p;  cudaGetSymbolAddress((void**)&zb2_p,  g_zb2);
    float*         inv_p;  cudaGetSymbolAddress((void**)&inv_p,  g_inv);
    int*           cnt_p;  cudaGetSymbolAddress((void**)&cnt_p,  g_cnt);
    int*           off_p;  cudaGetSymbolAddress((void**)&off_p,  g_off);
    int*           cur_p;  cudaGetSymbolAddress((void**)&cur_p,  g_cur);
    int*           bsum_p; cudaGetSymbolAddress((void**)&bsum_p, g_bsum);
    int*           bofs_p; cudaGetSymbolAddress((void**)&bofs_p, g_bofs);
    int*           srcs_p; cudaGetSymbolAddress((void**)&srcs_p, g_srcs);
    float*         wat_p;  cudaGetSymbolAddress((void**)&wat_p,  g_WaT);

    // --- fork side stream: CSR build + Wa1 transpose (hides under GEMM1+GEMM2) ---
    cudaStream_t side;
    cudaStreamCreateWithFlags(&side, cudaStreamNonBlocking);
    cudaEvent_t ev_fork, ev_csr;
    cudaEventCreateWithFlags(&ev_fork, cudaEventDisableTiming);
    cudaEventCreateWithFlags(&ev_csr,  cudaEventDisableTiming);

    cudaEventRecord(ev_fork, 0);
    cudaStreamWaitEvent(side, ev_fork, 0);

    transpose_wa1_kernel<<<(OUT_D * ATT_H + 255) / 256, 256, 0, side>>>(Wa1, wat_p);
    count_kernel<<<(E / 4 + 255) / 256, 256, 0, side>>>(tgt, cnt_p, E);
    scan1_kernel<<<SCAN_BLOCKS, SCAN_TPB, 0, side>>>(cnt_p, bsum_p);
    scan2_kernel<<<1, 64, 0, side>>>(bsum_p, bofs_p, off_p);
    scan3_kernel<<<SCAN_BLOCKS, SCAN_TPB, 0, side>>>(cnt_p, bofs_p, off_p, cur_p, inv_p);
    fill_kernel<<<(E / 4 + 255) / 256, 256, 0, side>>>(src, tgt, cur_p, srcs_p, E);
    cudaEventRecord(ev_csr, side);

    // main: h = relu(x @ W1^T + b1)   (256-wide, fp32 only)
    {
        dim3 grid(HID / GBN, (NNODES + GBM - 1) / GBM);
        gemm_tf32_kernel<<<grid, 256>>>(x, W1, b1, h_p, (__nv_bfloat16*)nullptr,
                                        NNODES, HID, F_IN, /*relu=*/1);
    }
    // main: z = h @ W2^T  (128-wide, NO bias/relu — commuted past propagation), + bf16 shadow
    {
        dim3 grid(OUT_D / GBN, (NNODES + GBM - 1) / GBM);
        gemm_tf32_kernel<<<grid, 256>>>(h_p, W2, (const float*)nullptr, z_p, zb_p,
                                        NNODES, OUT_D, HID, /*relu=*/0);
    }

    cudaStreamWaitEvent(0, ev_csr, 0);

    // propagation in 128-wide z-space: z2 = P z ; out = relu(P z2 + b2)
    {
        int gblocks = (NNODES + 7) / 8;
        gather_combine128_kernel<<<gblocks, 256>>>(z_p, zb_p, z2_p, zb2_p,
                                                   (const float*)nullptr,
                                                   off_p, srcs_p, inv_p);
        gather_combine128_kernel<<<gblocks, 256>>>(z2_p, zb2_p, out_ptr,
                                                   (__nv_bfloat16*)nullptr, b2,
                                                   off_p, srcs_p, inv_p);
    }

    attention_kernel<<<(NNODES * 32 + 255) / 256, 256>>>(out_ptr, wat_p, ba1, Wa2, ba2,
                                                         att_ptr, NNODES);

    cudaEventDestroy(ev_fork);
    cudaEventDestroy(ev_csr);
    cudaStreamDestroy(side);
}